// round 8
// baseline (speedup 1.0000x reference)
#include <cuda_runtime.h>
#include <cuda_bf16.h>
#include <math.h>
#include <stdint.h>

#define BATCH 32
#define LSEQ  2000
#define DIM   1024
#define KEEP  500
#define MROWS (BATCH*KEEP)           // 16000
#define NMASK (BATCH*(LSEQ-KEEP))    // 48000
#define LN_EPS 1e-5f

// GEMM tiling: CTA 64x128, 4 warps of 32x64, KC=32, 2 stages, 3 CTAs/SM
#define MT 64
#define NT 128
#define KC 32
#define NSTAGE (DIM/KC)              // 32
#define ROWB 80                      // padded smem row bytes
#define A_SPL (64*ROWB)              // 5120
#define B_SPL (128*ROWB)             // 10240
#define STAGE_B (2*A_SPL + 2*B_SPL)  // 30720 (Ahi,Alo,Bhi,Blo)
#define SMEM_TOTAL (2*STAGE_B)       // 61440

// -------- scratch (device globals) --------
__device__ int   g_rank[BATCH*LSEQ];
__device__ int   g_keep[BATCH*KEEP];
__device__ __align__(16) __nv_bfloat16 g_Ahi[MROWS*DIM];
__device__ __align__(16) __nv_bfloat16 g_Alo[MROWS*DIM];
__device__ __align__(16) __nv_bfloat16 g_Bhi[DIM*DIM];   // [n][k] = W_dec[k][n]
__device__ __align__(16) __nv_bfloat16 g_Blo[DIM*DIM];
__device__ __align__(16) float g_gw[DIM];                // gamma2*W_pred
__device__ float g_consts[2];                            // {sum(g2*Wp), sum(be2*Wp)+bp}
__device__ float g_part[3*8*MROWS];                      // [stat][ntile][row]
__device__ float g_s[MROWS+1];
__device__ float g_losspart[BATCH];

// =============================== PTX helpers ===============================
__device__ __forceinline__ uint32_t s2u(const void* p) {
    uint32_t a;
    asm("{ .reg .u64 t; cvta.to.shared.u64 t, %1; cvt.u32.u64 %0, t; }" : "=r"(a) : "l"(p));
    return a;
}
__device__ __forceinline__ void cp16(uint32_t s, const void* g) {
    asm volatile("cp.async.cg.shared.global [%0], [%1], 16;" :: "r"(s), "l"(g) : "memory");
}
__device__ __forceinline__ void ldm4(uint32_t* r, uint32_t addr) {
    asm volatile("ldmatrix.sync.aligned.m8n8.x4.shared.b16 {%0,%1,%2,%3}, [%4];"
                 : "=r"(r[0]), "=r"(r[1]), "=r"(r[2]), "=r"(r[3]) : "r"(addr));
}
__device__ __forceinline__ void mma16816(float* c, const uint32_t* a, const uint32_t* b) {
    asm volatile(
        "mma.sync.aligned.m16n8k16.row.col.f32.bf16.bf16.f32 "
        "{%0,%1,%2,%3}, {%4,%5,%6,%7}, {%8,%9}, {%0,%1,%2,%3};"
        : "+f"(c[0]), "+f"(c[1]), "+f"(c[2]), "+f"(c[3])
        : "r"(a[0]), "r"(a[1]), "r"(a[2]), "r"(a[3]), "r"(b[0]), "r"(b[1]));
}

// ===== Kernel 1 (fused setup): rank (256 blocks) + prep_b (1024) + consts (1) =====
__global__ void setup_kernel(const float* __restrict__ noise,
                             const float* __restrict__ Wd,
                             const float* __restrict__ g2,
                             const float* __restrict__ be2,
                             const float* __restrict__ Wp,
                             const float* __restrict__ bp)
{
    __shared__ float sh[LSEQ];
    const int bid = blockIdx.x, tid = threadIdx.x;

    if (bid < 256) {
        const int b = bid >> 3, seg = bid & 7;
        const float* nrow = noise + b*LSEQ;
        for (int i = tid; i < LSEQ; i += 256) sh[i] = nrow[i];
        __syncthreads();
        const int j = seg*250 + tid;
        if (tid >= 250) return;
        const float nj = sh[j];
        int r = 0;
        #pragma unroll 4
        for (int k = 0; k < LSEQ; ++k) {
            float nk = sh[k];
            r += (nk < nj) || (nk == nj && k < j);
        }
        g_rank[b*LSEQ + j] = r;
        if (r < KEEP) g_keep[b*KEEP + r] = j;
    } else if (bid < 1280) {
        const int bb = bid - 256, bx = bb & 31, by = bb >> 5;
        float (*t)[33] = (float(*)[33])sh;
        const int tx = tid & 31, ty = tid >> 5;
        #pragma unroll
        for (int j = 0; j < 32; j += 8)
            t[ty+j][tx] = Wd[(size_t)(by*32 + ty + j)*DIM + bx*32 + tx];
        __syncthreads();
        #pragma unroll
        for (int j = 0; j < 32; j += 8) {
            float v = t[tx][ty+j];
            size_t o = (size_t)(bx*32 + ty + j)*DIM + by*32 + tx;  // [n][k]
            __nv_bfloat16 h = __float2bfloat16(v);
            g_Bhi[o] = h;
            g_Blo[o] = __float2bfloat16(v - __bfloat162float(h));
        }
    } else {
        float sg = 0.f, sb = 0.f;
        #pragma unroll
        for (int i = 0; i < 4; ++i) {
            int d = tid + i*256;
            float w = Wp[d];
            float gv = g2[d]*w;
            g_gw[d] = gv;
            sg += gv;
            sb += be2[d]*w;
        }
        float* r1 = sh; float* r2 = sh + 256;
        r1[tid] = sg; r2[tid] = sb; __syncthreads();
        #pragma unroll
        for (int o = 128; o > 0; o >>= 1) {
            if (tid < o) { r1[tid] += r1[tid+o]; r2[tid] += r2[tid+o]; }
            __syncthreads();
        }
        if (tid == 0) { g_consts[0] = r1[0]; g_consts[1] = r2[0] + bp[0]; }
    }
}

// ===== Kernel 2: gather + encode + LN1 -> bf16 split A (+latent0), warp/row =====
__global__ void enc_ln_kernel(const float* __restrict__ expr,
                              const int*   __restrict__ idx,
                              const float* __restrict__ pos,
                              const float* __restrict__ cls,
                              const float* __restrict__ w_enc,
                              const float* __restrict__ b_enc,
                              const float* __restrict__ g1,
                              const float* __restrict__ be1,
                              float* __restrict__ out_lat0)
{
    const int g = blockIdx.x*8 + (threadIdx.x >> 5);   // 0..16031
    const int lane = threadIdx.x & 31;
    const int b = g / (KEEP+1);
    const int tt = g - b*(KEEP+1);                     // 0 = cls row

    float4 v[8];
    if (tt == 0) {
        #pragma unroll
        for (int i = 0; i < 8; ++i) {
            const int e4 = lane + i*32;
            float4 c = ((const float4*)cls)[e4];
            float4 p = ((const float4*)pos)[e4];
            v[i].x = c.x + p.x; v[i].y = c.y + p.y;
            v[i].z = c.z + p.z; v[i].w = c.w + p.w;
        }
    } else {
        const int j = g_keep[b*KEEP + tt - 1];
        const float e = expr[b*LSEQ + j];
        const float* prow = pos + (size_t)idx[b*LSEQ + j]*DIM;
        #pragma unroll
        for (int i = 0; i < 8; ++i) {
            const int e4 = lane + i*32;
            float4 p  = ((const float4*)prow)[e4];
            float4 w  = ((const float4*)w_enc)[e4];
            float4 bb = ((const float4*)b_enc)[e4];
            v[i].x = fmaf(e, w.x, bb.x) + p.x;
            v[i].y = fmaf(e, w.y, bb.y) + p.y;
            v[i].z = fmaf(e, w.z, bb.z) + p.z;
            v[i].w = fmaf(e, w.w, bb.w) + p.w;
        }
    }

    float s = 0.f, sq = 0.f;
    #pragma unroll
    for (int i = 0; i < 8; ++i) {
        s  += v[i].x + v[i].y + v[i].z + v[i].w;
        sq += v[i].x*v[i].x + v[i].y*v[i].y + v[i].z*v[i].z + v[i].w*v[i].w;
    }
    #pragma unroll
    for (int o = 16; o; o >>= 1) {
        s  += __shfl_xor_sync(0xFFFFFFFFu, s,  o);
        sq += __shfl_xor_sync(0xFFFFFFFFu, sq, o);
    }
    const float mean = s * (1.0f/DIM);
    const float var  = sq * (1.0f/DIM) - mean*mean;
    const float inv  = rsqrtf(var + LN_EPS);

    if (tt == 0) {
        float* dst = out_lat0 + b*DIM;
        #pragma unroll
        for (int i = 0; i < 8; ++i) {
            const int e4 = lane + i*32;
            const float4 gg = ((const float4*)g1)[e4];
            const float4 be = ((const float4*)be1)[e4];
            dst[e4*4+0] = (v[i].x - mean)*inv*gg.x + be.x;
            dst[e4*4+1] = (v[i].y - mean)*inv*gg.y + be.y;
            dst[e4*4+2] = (v[i].z - mean)*inv*gg.z + be.z;
            dst[e4*4+3] = (v[i].w - mean)*inv*gg.w + be.w;
        }
    } else {
        const size_t row = (size_t)(b*KEEP + tt - 1)*DIM;
        #pragma unroll
        for (int i = 0; i < 8; ++i) {
            const int e4 = lane + i*32;
            const float4 gg = ((const float4*)g1)[e4];
            const float4 be = ((const float4*)be1)[e4];
            float r0 = (v[i].x - mean)*inv*gg.x + be.x;
            float r1 = (v[i].y - mean)*inv*gg.y + be.y;
            float r2 = (v[i].z - mean)*inv*gg.z + be.z;
            float r3 = (v[i].w - mean)*inv*gg.w + be.w;
            __nv_bfloat16 h0 = __float2bfloat16(r0), h1 = __float2bfloat16(r1);
            __nv_bfloat16 h2 = __float2bfloat16(r2), h3 = __float2bfloat16(r3);
            __nv_bfloat162 hA; hA.x = h0; hA.y = h1;
            __nv_bfloat162 hB; hB.x = h2; hB.y = h3;
            ((__nv_bfloat162*)(g_Ahi + row))[e4*2+0] = hA;
            ((__nv_bfloat162*)(g_Ahi + row))[e4*2+1] = hB;
            __nv_bfloat162 lA, lB;
            lA.x = __float2bfloat16(r0 - __bfloat162float(h0));
            lA.y = __float2bfloat16(r1 - __bfloat162float(h1));
            lB.x = __float2bfloat16(r2 - __bfloat162float(h2));
            lB.y = __float2bfloat16(r3 - __bfloat162float(h3));
            ((__nv_bfloat162*)(g_Alo + row))[e4*2+0] = lA;
            ((__nv_bfloat162*)(g_Alo + row))[e4*2+1] = lB;
        }
    }
}

// ====== Kernel 3: HMMA split-bf16 GEMM, CTA 64x128, warps 32x64 ======
__device__ __forceinline__ void load_stage(uint32_t sb, int stage, int bm, int bn, int tid)
{
    const uint32_t st = sb + (uint32_t)(stage & 1) * STAGE_B;
    const int kbase = stage * KC;
    #pragma unroll
    for (int i = 0; i < 12; ++i) {
        const int id = i*128 + tid;           // 0..1535
        const __nv_bfloat16* src;
        uint32_t dst;
        if (id < 512) {                       // A hi/lo: 64 rows x 4 segs x 2 splits
            const int split = id >> 8, u = id & 255, r = u >> 2, seg = u & 3;
            src = (split ? g_Alo : g_Ahi) + (size_t)(bm + r)*DIM + kbase + seg*8;
            dst = st + (uint32_t)(split*A_SPL + r*ROWB + seg*16);
        } else {                              // B hi/lo: 128 rows x 4 segs x 2 splits
            const int t = id - 512;
            const int split = t >> 9, u = t & 511, r = u >> 2, seg = u & 3;
            src = (split ? g_Blo : g_Bhi) + (size_t)(bn + r)*DIM + kbase + seg*8;
            dst = st + (uint32_t)(2*A_SPL + split*B_SPL + r*ROWB + seg*16);
        }
        cp16(dst, src);
    }
    asm volatile("cp.async.commit_group;" ::: "memory");
}

__global__ void __launch_bounds__(128, 3)
gemm_tc_kernel(const float* __restrict__ bias)
{
    extern __shared__ char sm_[];
    const uint32_t sb = s2u(sm_);
    const int tid = threadIdx.x, wid = tid >> 5, lane = tid & 31;
    const int wm = wid & 1, wn = wid >> 1;     // 2x2 warps of 32x64
    const int bn = blockIdx.x * NT;            // 0..7 N-tiles
    const int bm = blockIdx.y * MT;            // 0..249 M-tiles

    const uint32_t aOff = (uint32_t)((wm*32 + (lane & 15))*ROWB + (lane >> 4)*16);
    const uint32_t bOff = (uint32_t)(2*A_SPL
                       + (wn*64 + (lane & 7) + (lane >> 4)*8)*ROWB
                       + ((lane >> 3) & 1)*16);

    float acc[2][8][4] = {};
    load_stage(sb, 0, bm, bn, tid);

    for (int s = 0; s < NSTAGE; ++s) {
        asm volatile("cp.async.wait_group 0;" ::: "memory");
        __syncthreads();

        const uint32_t st = sb + (uint32_t)(s & 1) * STAGE_B;

        // ---- ks = 0: issue ALL frag loads up front ----
        uint32_t Ah[2][4], Al[2][4], Bh[4][4], Bl[4][4];
        #pragma unroll
        for (int mi = 0; mi < 2; ++mi) {
            ldm4(Ah[mi], st + aOff + (uint32_t)(mi*16*ROWB));
            ldm4(Al[mi], st + aOff + (uint32_t)(A_SPL + mi*16*ROWB));
        }
        #pragma unroll
        for (int np = 0; np < 4; ++np) {
            ldm4(Bh[np], st + bOff + (uint32_t)(np*16*ROWB));
            ldm4(Bl[np], st + bOff + (uint32_t)(B_SPL + np*16*ROWB));
        }
        // prefetch next stage while ks=0 math runs
        if (s + 1 < NSTAGE) load_stage(sb, s + 1, bm, bn, tid);

        #pragma unroll
        for (int mi = 0; mi < 2; ++mi)
            #pragma unroll
            for (int ni = 0; ni < 8; ++ni)
                mma16816(acc[mi][ni], Ah[mi], &Bh[ni>>1][(ni&1)*2]);
        #pragma unroll
        for (int mi = 0; mi < 2; ++mi)
            #pragma unroll
            for (int ni = 0; ni < 8; ++ni)
                mma16816(acc[mi][ni], Ah[mi], &Bl[ni>>1][(ni&1)*2]);
        #pragma unroll
        for (int mi = 0; mi < 2; ++mi)
            #pragma unroll
            for (int ni = 0; ni < 8; ++ni)
                mma16816(acc[mi][ni], Al[mi], &Bh[ni>>1][(ni&1)*2]);

        // ---- ks = 1 ----
        #pragma unroll
        for (int mi = 0; mi < 2; ++mi) {
            ldm4(Ah[mi], st + aOff + (uint32_t)(mi*16*ROWB) + 32u);
            ldm4(Al[mi], st + aOff + (uint32_t)(A_SPL + mi*16*ROWB) + 32u);
        }
        #pragma unroll
        for (int np = 0; np < 4; ++np) {
            ldm4(Bh[np], st + bOff + (uint32_t)(np*16*ROWB) + 32u);
            ldm4(Bl[np], st + bOff + (uint32_t)(B_SPL + np*16*ROWB) + 32u);
        }
        #pragma unroll
        for (int mi = 0; mi < 2; ++mi)
            #pragma unroll
            for (int ni = 0; ni < 8; ++ni)
                mma16816(acc[mi][ni], Ah[mi], &Bh[ni>>1][(ni&1)*2]);
        #pragma unroll
        for (int mi = 0; mi < 2; ++mi)
            #pragma unroll
            for (int ni = 0; ni < 8; ++ni)
                mma16816(acc[mi][ni], Ah[mi], &Bl[ni>>1][(ni&1)*2]);
        #pragma unroll
        for (int mi = 0; mi < 2; ++mi)
            #pragma unroll
            for (int ni = 0; ni < 8; ++ni)
                mma16816(acc[mi][ni], Al[mi], &Bh[ni>>1][(ni&1)*2]);
    }

    // ---- fused epilogue: per-row partial S1,S2,S3 over this CTA's 128 cols ----
    __syncthreads();
    float* sred = (float*)sm_;             // [2 wn][64 rows][3]

    const int c2 = (lane & 3)*2;
    const int r4 = lane >> 2;
    float st1[2][2] = {}, st2[2][2] = {}, st3[2][2] = {};
    #pragma unroll
    for (int ni = 0; ni < 8; ++ni) {
        const int n = bn + wn*64 + ni*8 + c2;
        const float2 bv = *(const float2*)(bias + n);
        const float2 gv = *(const float2*)(g_gw + n);
        #pragma unroll
        for (int mi = 0; mi < 2; ++mi) {
            float x0 = acc[mi][ni][0] + bv.x;
            float x1 = acc[mi][ni][1] + bv.y;
            float x2 = acc[mi][ni][2] + bv.x;
            float x3 = acc[mi][ni][3] + bv.y;
            st1[mi][0] += x0 + x1;           st1[mi][1] += x2 + x3;
            st2[mi][0] += x0*x0 + x1*x1;     st2[mi][1] += x2*x2 + x3*x3;
            st3[mi][0] += x0*gv.x + x1*gv.y; st3[mi][1] += x2*gv.x + x3*gv.y;
        }
    }
    #pragma unroll
    for (int mi = 0; mi < 2; ++mi)
        #pragma unroll
        for (int h = 0; h < 2; ++h) {
            #pragma unroll
            for (int o = 1; o < 4; o <<= 1) {
                st1[mi][h] += __shfl_xor_sync(0xFFFFFFFFu, st1[mi][h], o);
                st2[mi][h] += __shfl_xor_sync(0xFFFFFFFFu, st2[mi][h], o);
                st3[mi][h] += __shfl_xor_sync(0xFFFFFFFFu, st3[mi][h], o);
            }
        }
    if ((lane & 3) == 0) {
        #pragma unroll
        for (int mi = 0; mi < 2; ++mi)
            #pragma unroll
            for (int h = 0; h < 2; ++h) {
                const int row = wm*32 + mi*16 + h*8 + r4;
                float* p = sred + (wn*64 + row)*3;
                p[0] = st1[mi][h]; p[1] = st2[mi][h]; p[2] = st3[mi][h];
            }
    }
    __syncthreads();
    if (tid < 64) {
        const int m = bm + tid;
        const int t8 = blockIdx.x;
        #pragma unroll
        for (int c = 0; c < 3; ++c)
            g_part[(c*8 + t8)*MROWS + m] =
                sred[(0*64 + tid)*3 + c] + sred[(1*64 + tid)*3 + c];
    }
}

// ===== Kernel 4 (fused): combine partials (blocks 0..62) + mask_token pred (63) =====
__global__ void combine_mask_kernel(const float* __restrict__ mask_token,
                                    const float* __restrict__ g2,
                                    const float* __restrict__ be2,
                                    const float* __restrict__ Wp,
                                    const float* __restrict__ bp)
{
    const int tid = threadIdx.x;
    if (blockIdx.x < 63) {
        const int m = blockIdx.x*256 + tid;
        if (m >= MROWS) return;
        float S1 = 0.f, S2 = 0.f, S3 = 0.f;
        #pragma unroll
        for (int t = 0; t < 8; ++t) {
            S1 += g_part[(0*8 + t)*MROWS + m];
            S2 += g_part[(1*8 + t)*MROWS + m];
            S3 += g_part[(2*8 + t)*MROWS + m];
        }
        const float mean = S1 * (1.0f/DIM);
        const float var  = S2 * (1.0f/DIM) - mean*mean;
        const float inv  = rsqrtf(var + LN_EPS);
        g_s[m] = inv*(S3 - mean*g_consts[0]) + g_consts[1];
    } else {
        float v[4];
        #pragma unroll
        for (int i = 0; i < 4; ++i) v[i] = mask_token[tid + i*256];

        __shared__ float red[256];
        float s = v[0]+v[1]+v[2]+v[3];
        red[tid] = s; __syncthreads();
        #pragma unroll
        for (int o = 128; o > 0; o >>= 1) { if (tid < o) red[tid] += red[tid+o]; __syncthreads(); }
        const float mean = red[0] * (1.0f/DIM);
        __syncthreads();
        float sv = 0.f;
        #pragma unroll
        for (int i = 0; i < 4; ++i) { float dv = v[i]-mean; sv += dv*dv; }
        red[tid] = sv; __syncthreads();
        #pragma unroll
        for (int o = 128; o > 0; o >>= 1) { if (tid < o) red[tid] += red[tid+o]; __syncthreads(); }
        const float inv = rsqrtf(red[0]*(1.0f/DIM) + LN_EPS);
        __syncthreads();
        float part = 0.f;
        #pragma unroll
        for (int i = 0; i < 4; ++i) {
            int d = tid + i*256;
            part += ((v[i]-mean)*inv*g2[d] + be2[d]) * Wp[d];
        }
        red[tid] = part; __syncthreads();
        #pragma unroll
        for (int o = 128; o > 0; o >>= 1) { if (tid < o) red[tid] += red[tid+o]; __syncthreads(); }
        if (tid == 0) g_s[MROWS] = red[0] + bp[0];
    }
}

// ===== Kernel 5: scatter pred/mask + per-batch loss partial =====
__global__ void out_kernel(const float* __restrict__ expr,
                           float* __restrict__ out_pred,
                           float* __restrict__ out_mask)
{
    const int b = blockIdx.x;
    const float cm = g_s[MROWS];
    float part = 0.f;
    for (int l = threadIdx.x; l < LSEQ; l += blockDim.x) {
        const int r = g_rank[b*LSEQ + l];
        const bool masked = (r >= KEEP);
        const float p = masked ? cm : g_s[b*KEEP + r];
        out_pred[b*LSEQ + l] = p;
        out_mask[b*LSEQ + l] = masked ? 1.0f : 0.0f;
        if (masked) {
            float t = expr[b*LSEQ + l];
            if (isnan(t)) t = 0.f;
            const float d = p - t;
            part += d*d;
        }
    }
    __shared__ float red[256];
    red[threadIdx.x] = part; __syncthreads();
    #pragma unroll
    for (int o = 128; o > 0; o >>= 1) {
        if (threadIdx.x < o) red[threadIdx.x] += red[threadIdx.x+o];
        __syncthreads();
    }
    if (threadIdx.x == 0) g_losspart[b] = red[0];
}

// ===== Kernel 6: final loss =====
__global__ void loss_kernel(float* __restrict__ out)
{
    if (threadIdx.x == 0) {
        float s = 0.f;
        for (int i = 0; i < BATCH; ++i) s += g_losspart[i];
        out[0] = s / (float)NMASK;
    }
}

// =============================== launch ===============================
extern "C" void kernel_launch(void* const* d_in, const int* in_sizes, int n_in,
                              void* d_out, int out_size)
{
    const float* expr      = (const float*)d_in[0];
    const int*   idx       = (const int*)  d_in[1];
    const float* noise     = (const float*)d_in[2];
    const float* pos_table = (const float*)d_in[3];
    const float* cls_token = (const float*)d_in[4];
    const float* w_enc     = (const float*)d_in[5];
    const float* b_enc     = (const float*)d_in[6];
    const float* gamma1    = (const float*)d_in[7];
    const float* beta1     = (const float*)d_in[8];
    const float* W_dec     = (const float*)d_in[9];
    const float* b_dec     = (const float*)d_in[10];
    const float* mask_tok  = (const float*)d_in[11];
    const float* gamma2    = (const float*)d_in[12];
    const float* beta2     = (const float*)d_in[13];
    const float* W_pred    = (const float*)d_in[14];
    const float* b_pred    = (const float*)d_in[15];

    float* out = (float*)d_out;
    float* out_loss  = out;
    float* out_pred  = out + 1;
    float* out_mask  = out + 1 + BATCH*LSEQ;
    float* out_lat0  = out + 1 + 2*BATCH*LSEQ;

    cudaFuncSetAttribute(gemm_tc_kernel,
                         cudaFuncAttributeMaxDynamicSharedMemorySize, SMEM_TOTAL);

    setup_kernel<<<1281, 256>>>(noise, W_dec, gamma2, beta2, W_pred, b_pred);
    enc_ln_kernel<<<(BATCH*(KEEP+1))/8, 256>>>(expr, idx, pos_table, cls_token,
                                               w_enc, b_enc, gamma1, beta1, out_lat0);
    gemm_tc_kernel<<<dim3(DIM/NT, MROWS/MT), 128, SMEM_TOTAL>>>(b_dec);
    combine_mask_kernel<<<64, 256>>>(mask_tok, gamma2, beta2, W_pred, b_pred);
    out_kernel<<<BATCH, 256>>>(expr, out_pred, out_mask);
    loss_kernel<<<1, 32>>>(out_loss);
}

// round 9
// speedup vs baseline: 1.1313x; 1.1313x over previous
#include <cuda_runtime.h>
#include <cuda_bf16.h>
#include <math.h>
#include <stdint.h>

#define BATCH 32
#define LSEQ  2000
#define DIM   1024
#define KEEP  500
#define MROWS (BATCH*KEEP)           // 16000
#define NMASK (BATCH*(LSEQ-KEEP))    // 48000
#define LN_EPS 1e-5f

// GEMM tiling: CTA 128x128, 4 warps of 64x64, KC=32, 2 stages, 2 CTAs/SM
#define MT 128
#define NT 128
#define KC 32
#define NSTAGE (DIM/KC)              // 32
#define NTILES ((MROWS/MT)*(DIM/NT)) // 1000
#define ROWB 80                      // padded smem row bytes
#define SPLIT_B (128*ROWB)           // 10240
#define STAGE_B (4*SPLIT_B)          // 40960 (Ahi,Alo,Bhi,Blo)
#define SMEM_TOTAL (2*STAGE_B)       // 81920
#define GEMM_GRID 296                // persistent

// -------- scratch (device globals) --------
__device__ int   g_rank[BATCH*LSEQ];
__device__ int   g_keep[BATCH*KEEP];
__device__ __align__(16) __nv_bfloat16 g_Ahi[MROWS*DIM];
__device__ __align__(16) __nv_bfloat16 g_Alo[MROWS*DIM];
__device__ __align__(16) __nv_bfloat16 g_Bhi[DIM*DIM];   // [n][k] = W_dec[k][n]
__device__ __align__(16) __nv_bfloat16 g_Blo[DIM*DIM];
__device__ __align__(16) float g_gw[DIM];                // gamma2*W_pred
__device__ float g_consts[2];                            // {sum(g2*Wp), sum(be2*Wp)+bp}
__device__ float g_part[3*8*MROWS];                      // [stat][ntile][row]
__device__ float g_s[MROWS+1];
__device__ float g_losspart[BATCH];

// =============================== PTX helpers ===============================
__device__ __forceinline__ uint32_t s2u(const void* p) {
    uint32_t a;
    asm("{ .reg .u64 t; cvta.to.shared.u64 t, %1; cvt.u32.u64 %0, t; }" : "=r"(a) : "l"(p));
    return a;
}
__device__ __forceinline__ void cp16(uint32_t s, const void* g) {
    asm volatile("cp.async.cg.shared.global [%0], [%1], 16;" :: "r"(s), "l"(g) : "memory");
}
__device__ __forceinline__ void ldm4(uint32_t* r, uint32_t addr) {
    asm volatile("ldmatrix.sync.aligned.m8n8.x4.shared.b16 {%0,%1,%2,%3}, [%4];"
                 : "=r"(r[0]), "=r"(r[1]), "=r"(r[2]), "=r"(r[3]) : "r"(addr));
}
__device__ __forceinline__ void mma16816(float* c, const uint32_t* a, const uint32_t* b) {
    asm volatile(
        "mma.sync.aligned.m16n8k16.row.col.f32.bf16.bf16.f32 "
        "{%0,%1,%2,%3}, {%4,%5,%6,%7}, {%8,%9}, {%0,%1,%2,%3};"
        : "+f"(c[0]), "+f"(c[1]), "+f"(c[2]), "+f"(c[3])
        : "r"(a[0]), "r"(a[1]), "r"(a[2]), "r"(a[3]), "r"(b[0]), "r"(b[1]));
}

// ===== Kernel 1 (fused setup): rank (256 blocks) + prep_b (1024) + consts (1) =====
__global__ void setup_kernel(const float* __restrict__ noise,
                             const float* __restrict__ Wd,
                             const float* __restrict__ g2,
                             const float* __restrict__ be2,
                             const float* __restrict__ Wp,
                             const float* __restrict__ bp)
{
    __shared__ float sh[LSEQ];
    const int bid = blockIdx.x, tid = threadIdx.x;

    if (bid < 256) {
        const int b = bid >> 3, seg = bid & 7;
        const float* nrow = noise + b*LSEQ;
        for (int i = tid; i < LSEQ; i += 256) sh[i] = nrow[i];
        __syncthreads();
        const int j = seg*250 + tid;
        if (tid >= 250) return;
        const float nj = sh[j];
        int r = 0;
        #pragma unroll 4
        for (int k = 0; k < LSEQ; ++k) {
            float nk = sh[k];
            r += (nk < nj) || (nk == nj && k < j);
        }
        g_rank[b*LSEQ + j] = r;
        if (r < KEEP) g_keep[b*KEEP + r] = j;
    } else if (bid < 1280) {
        const int bb = bid - 256, bx = bb & 31, by = bb >> 5;
        float (*t)[33] = (float(*)[33])sh;
        const int tx = tid & 31, ty = tid >> 5;
        #pragma unroll
        for (int j = 0; j < 32; j += 8)
            t[ty+j][tx] = Wd[(size_t)(by*32 + ty + j)*DIM + bx*32 + tx];
        __syncthreads();
        #pragma unroll
        for (int j = 0; j < 32; j += 8) {
            float v = t[tx][ty+j];
            size_t o = (size_t)(bx*32 + ty + j)*DIM + by*32 + tx;  // [n][k]
            __nv_bfloat16 h = __float2bfloat16(v);
            g_Bhi[o] = h;
            g_Blo[o] = __float2bfloat16(v - __bfloat162float(h));
        }
    } else {
        float sg = 0.f, sb = 0.f;
        #pragma unroll
        for (int i = 0; i < 4; ++i) {
            int d = tid + i*256;
            float w = Wp[d];
            float gv = g2[d]*w;
            g_gw[d] = gv;
            sg += gv;
            sb += be2[d]*w;
        }
        float* r1 = sh; float* r2 = sh + 256;
        r1[tid] = sg; r2[tid] = sb; __syncthreads();
        #pragma unroll
        for (int o = 128; o > 0; o >>= 1) {
            if (tid < o) { r1[tid] += r1[tid+o]; r2[tid] += r2[tid+o]; }
            __syncthreads();
        }
        if (tid == 0) { g_consts[0] = r1[0]; g_consts[1] = r2[0] + bp[0]; }
    }
}

// ===== Kernel 2: gather + encode + LN1 -> bf16 split A (+latent0), warp/row =====
__global__ void enc_ln_kernel(const float* __restrict__ expr,
                              const int*   __restrict__ idx,
                              const float* __restrict__ pos,
                              const float* __restrict__ cls,
                              const float* __restrict__ w_enc,
                              const float* __restrict__ b_enc,
                              const float* __restrict__ g1,
                              const float* __restrict__ be1,
                              float* __restrict__ out_lat0)
{
    const int g = blockIdx.x*8 + (threadIdx.x >> 5);   // 0..16031
    const int lane = threadIdx.x & 31;
    const int b = g / (KEEP+1);
    const int tt = g - b*(KEEP+1);                     // 0 = cls row

    float4 v[8];
    if (tt == 0) {
        #pragma unroll
        for (int i = 0; i < 8; ++i) {
            const int e4 = lane + i*32;
            float4 c = ((const float4*)cls)[e4];
            float4 p = ((const float4*)pos)[e4];
            v[i].x = c.x + p.x; v[i].y = c.y + p.y;
            v[i].z = c.z + p.z; v[i].w = c.w + p.w;
        }
    } else {
        const int j = g_keep[b*KEEP + tt - 1];
        const float e = expr[b*LSEQ + j];
        const float* prow = pos + (size_t)idx[b*LSEQ + j]*DIM;
        #pragma unroll
        for (int i = 0; i < 8; ++i) {
            const int e4 = lane + i*32;
            float4 p  = ((const float4*)prow)[e4];
            float4 w  = ((const float4*)w_enc)[e4];
            float4 bb = ((const float4*)b_enc)[e4];
            v[i].x = fmaf(e, w.x, bb.x) + p.x;
            v[i].y = fmaf(e, w.y, bb.y) + p.y;
            v[i].z = fmaf(e, w.z, bb.z) + p.z;
            v[i].w = fmaf(e, w.w, bb.w) + p.w;
        }
    }

    float s = 0.f, sq = 0.f;
    #pragma unroll
    for (int i = 0; i < 8; ++i) {
        s  += v[i].x + v[i].y + v[i].z + v[i].w;
        sq += v[i].x*v[i].x + v[i].y*v[i].y + v[i].z*v[i].z + v[i].w*v[i].w;
    }
    #pragma unroll
    for (int o = 16; o; o >>= 1) {
        s  += __shfl_xor_sync(0xFFFFFFFFu, s,  o);
        sq += __shfl_xor_sync(0xFFFFFFFFu, sq, o);
    }
    const float mean = s * (1.0f/DIM);
    const float var  = sq * (1.0f/DIM) - mean*mean;
    const float inv  = rsqrtf(var + LN_EPS);

    if (tt == 0) {
        float* dst = out_lat0 + b*DIM;
        #pragma unroll
        for (int i = 0; i < 8; ++i) {
            const int e4 = lane + i*32;
            const float4 gg = ((const float4*)g1)[e4];
            const float4 be = ((const float4*)be1)[e4];
            dst[e4*4+0] = (v[i].x - mean)*inv*gg.x + be.x;
            dst[e4*4+1] = (v[i].y - mean)*inv*gg.y + be.y;
            dst[e4*4+2] = (v[i].z - mean)*inv*gg.z + be.z;
            dst[e4*4+3] = (v[i].w - mean)*inv*gg.w + be.w;
        }
    } else {
        const size_t row = (size_t)(b*KEEP + tt - 1)*DIM;
        #pragma unroll
        for (int i = 0; i < 8; ++i) {
            const int e4 = lane + i*32;
            const float4 gg = ((const float4*)g1)[e4];
            const float4 be = ((const float4*)be1)[e4];
            float r0 = (v[i].x - mean)*inv*gg.x + be.x;
            float r1 = (v[i].y - mean)*inv*gg.y + be.y;
            float r2 = (v[i].z - mean)*inv*gg.z + be.z;
            float r3 = (v[i].w - mean)*inv*gg.w + be.w;
            __nv_bfloat16 h0 = __float2bfloat16(r0), h1 = __float2bfloat16(r1);
            __nv_bfloat16 h2 = __float2bfloat16(r2), h3 = __float2bfloat16(r3);
            __nv_bfloat162 hA; hA.x = h0; hA.y = h1;
            __nv_bfloat162 hB; hB.x = h2; hB.y = h3;
            ((__nv_bfloat162*)(g_Ahi + row))[e4*2+0] = hA;
            ((__nv_bfloat162*)(g_Ahi + row))[e4*2+1] = hB;
            __nv_bfloat162 lA, lB;
            lA.x = __float2bfloat16(r0 - __bfloat162float(h0));
            lA.y = __float2bfloat16(r1 - __bfloat162float(h1));
            lB.x = __float2bfloat16(r2 - __bfloat162float(h2));
            lB.y = __float2bfloat16(r3 - __bfloat162float(h3));
            ((__nv_bfloat162*)(g_Alo + row))[e4*2+0] = lA;
            ((__nv_bfloat162*)(g_Alo + row))[e4*2+1] = lB;
        }
    }
}

// ====== Kernel 3: persistent HMMA split-bf16 GEMM, software-pipelined frags ======
__device__ __forceinline__ void load_stage(uint32_t sb, int stage, int bm, int bn, int tid)
{
    const uint32_t st = sb + (uint32_t)(stage & 1) * STAGE_B;
    const int kbase = stage * KC;
    #pragma unroll
    for (int i = 0; i < 16; ++i) {
        const int id = i*128 + tid;           // 0..2047
        const int isB = id >> 10;
        const int t = id & 1023;
        const int split = t >> 9, u = t & 511, r = u >> 2, seg = u & 3;
        const __nv_bfloat16* src;
        uint32_t dst;
        if (!isB) {
            src = (split ? g_Alo : g_Ahi) + (size_t)(bm + r)*DIM + kbase + seg*8;
            dst = st + (uint32_t)(split*SPLIT_B + r*ROWB + seg*16);
        } else {
            src = (split ? g_Blo : g_Bhi) + (size_t)(bn + r)*DIM + kbase + seg*8;
            dst = st + (uint32_t)(2*SPLIT_B + split*SPLIT_B + r*ROWB + seg*16);
        }
        cp16(dst, src);
    }
    asm volatile("cp.async.commit_group;" ::: "memory");
}

__global__ void __launch_bounds__(128, 2)
gemm_tc_kernel(const float* __restrict__ bias)
{
    extern __shared__ char sm_[];
    const uint32_t sb = s2u(sm_);
    const int tid = threadIdx.x, wid = tid >> 5, lane = tid & 31;
    const int wm = wid & 1, wn = wid >> 1;     // 2x2 warps of 64x64

    const uint32_t aOff = (uint32_t)((wm*64 + (lane & 15))*ROWB + (lane >> 4)*16);
    const uint32_t bOff = (uint32_t)(2*SPLIT_B
                       + (wn*64 + (lane & 7) + (lane >> 4)*8)*ROWB
                       + ((lane >> 3) & 1)*16);
    const int c2 = (lane & 3)*2;
    const int r4 = lane >> 2;

    uint32_t Ah[4][4], Al[4][4], Bh[4][4], Bl[4][4];

    for (int tile = blockIdx.x; tile < NTILES; tile += GEMM_GRID) {
        const int bn = (tile & 7) * NT;
        const int bm = (tile >> 3) * MT;

        float acc[4][8][4] = {};
        __syncthreads();                 // prior tile's epilogue smem reads done
        load_stage(sb, 0, bm, bn, tid);
        load_stage(sb, 1, bm, bn, tid);
        asm volatile("cp.async.wait_group 1;" ::: "memory");
        __syncthreads();

        // preload ks0 frags of stage 0
        {
            const uint32_t st = sb;
            #pragma unroll
            for (int mi = 0; mi < 4; ++mi) {
                ldm4(Ah[mi], st + aOff + (uint32_t)(mi*16*ROWB));
                ldm4(Al[mi], st + aOff + (uint32_t)(SPLIT_B + mi*16*ROWB));
            }
            #pragma unroll
            for (int np = 0; np < 4; ++np) {
                ldm4(Bh[np], st + bOff + (uint32_t)(np*16*ROWB));
                ldm4(Bl[np], st + bOff + (uint32_t)(SPLIT_B + np*16*ROWB));
            }
        }

        for (int s = 0; s < NSTAGE; ++s) {
            const uint32_t st = sb + (uint32_t)(s & 1) * STAGE_B;

            // ---- MMAs for ks0 (frags preloaded) ----
            #pragma unroll
            for (int mi = 0; mi < 4; ++mi)
                #pragma unroll
                for (int ni = 0; ni < 8; ++ni)
                    mma16816(acc[mi][ni], Ah[mi], &Bh[ni>>1][(ni&1)*2]);
            #pragma unroll
            for (int mi = 0; mi < 4; ++mi)
                #pragma unroll
                for (int ni = 0; ni < 8; ++ni)
                    mma16816(acc[mi][ni], Ah[mi], &Bl[ni>>1][(ni&1)*2]);
            #pragma unroll
            for (int mi = 0; mi < 4; ++mi)
                #pragma unroll
                for (int ni = 0; ni < 8; ++ni)
                    mma16816(acc[mi][ni], Al[mi], &Bh[ni>>1][(ni&1)*2]);

            // ---- load ks1 frags (WAR on just-issued MMAs is scoreboarded) ----
            #pragma unroll
            for (int mi = 0; mi < 4; ++mi) {
                ldm4(Ah[mi], st + aOff + (uint32_t)(mi*16*ROWB) + 32u);
                ldm4(Al[mi], st + aOff + (uint32_t)(SPLIT_B + mi*16*ROWB) + 32u);
            }
            #pragma unroll
            for (int np = 0; np < 4; ++np) {
                ldm4(Bh[np], st + bOff + (uint32_t)(np*16*ROWB) + 32u);
                ldm4(Bl[np], st + bOff + (uint32_t)(SPLIT_B + np*16*ROWB) + 32u);
            }

            // ---- MMAs for ks1 ----
            #pragma unroll
            for (int mi = 0; mi < 4; ++mi)
                #pragma unroll
                for (int ni = 0; ni < 8; ++ni)
                    mma16816(acc[mi][ni], Ah[mi], &Bh[ni>>1][(ni&1)*2]);
            #pragma unroll
            for (int mi = 0; mi < 4; ++mi)
                #pragma unroll
                for (int ni = 0; ni < 8; ++ni)
                    mma16816(acc[mi][ni], Ah[mi], &Bl[ni>>1][(ni&1)*2]);
            #pragma unroll
            for (int mi = 0; mi < 4; ++mi)
                #pragma unroll
                for (int ni = 0; ni < 8; ++ni)
                    mma16816(acc[mi][ni], Al[mi], &Bh[ni>>1][(ni&1)*2]);

            if (s + 1 < NSTAGE) {
                // stage s+1 data must be resident; also all reads of stage s done
                asm volatile("cp.async.wait_group 0;" ::: "memory");
                __syncthreads();
                const uint32_t sn = sb + (uint32_t)((s+1) & 1) * STAGE_B;
                // preload ks0 frags of stage s+1
                #pragma unroll
                for (int mi = 0; mi < 4; ++mi) {
                    ldm4(Ah[mi], sn + aOff + (uint32_t)(mi*16*ROWB));
                    ldm4(Al[mi], sn + aOff + (uint32_t)(SPLIT_B + mi*16*ROWB));
                }
                #pragma unroll
                for (int np = 0; np < 4; ++np) {
                    ldm4(Bh[np], sn + bOff + (uint32_t)(np*16*ROWB));
                    ldm4(Bl[np], sn + bOff + (uint32_t)(SPLIT_B + np*16*ROWB));
                }
                // refill the buffer of stage s (now fully consumed)
                if (s + 2 < NSTAGE) load_stage(sb, s + 2, bm, bn, tid);
            }
        }

        // ---- fused epilogue: per-row partial S1,S2,S3 over this CTA's 128 cols ----
        __syncthreads();
        float* sred = (float*)sm_;             // [2 wn][128 rows][3]

        float st1[4][2] = {}, st2[4][2] = {}, st3[4][2] = {};
        #pragma unroll
        for (int ni = 0; ni < 8; ++ni) {
            const int n = bn + wn*64 + ni*8 + c2;
            const float2 bv = *(const float2*)(bias + n);
            const float2 gv = *(const float2*)(g_gw + n);
            #pragma unroll
            for (int mi = 0; mi < 4; ++mi) {
                float x0 = acc[mi][ni][0] + bv.x;
                float x1 = acc[mi][ni][1] + bv.y;
                float x2 = acc[mi][ni][2] + bv.x;
                float x3 = acc[mi][ni][3] + bv.y;
                st1[mi][0] += x0 + x1;           st1[mi][1] += x2 + x3;
                st2[mi][0] += x0*x0 + x1*x1;     st2[mi][1] += x2*x2 + x3*x3;
                st3[mi][0] += x0*gv.x + x1*gv.y; st3[mi][1] += x2*gv.x + x3*gv.y;
            }
        }
        #pragma unroll
        for (int mi = 0; mi < 4; ++mi)
            #pragma unroll
            for (int h = 0; h < 2; ++h) {
                #pragma unroll
                for (int o = 1; o < 4; o <<= 1) {
                    st1[mi][h] += __shfl_xor_sync(0xFFFFFFFFu, st1[mi][h], o);
                    st2[mi][h] += __shfl_xor_sync(0xFFFFFFFFu, st2[mi][h], o);
                    st3[mi][h] += __shfl_xor_sync(0xFFFFFFFFu, st3[mi][h], o);
                }
            }
        if ((lane & 3) == 0) {
            #pragma unroll
            for (int mi = 0; mi < 4; ++mi)
                #pragma unroll
                for (int h = 0; h < 2; ++h) {
                    const int row = wm*64 + mi*16 + h*8 + r4;
                    float* p = sred + (wn*128 + row)*3;
                    p[0] = st1[mi][h]; p[1] = st2[mi][h]; p[2] = st3[mi][h];
                }
        }
        __syncthreads();
        {
            const int m = bm + tid;
            const int t8 = tile & 7;
            #pragma unroll
            for (int c = 0; c < 3; ++c)
                g_part[(c*8 + t8)*MROWS + m] =
                    sred[(0*128 + tid)*3 + c] + sred[(1*128 + tid)*3 + c];
        }
    }
}

// ===== Kernel 4 (fused): combine partials (blocks 0..62) + mask_token pred (63) =====
__global__ void combine_mask_kernel(const float* __restrict__ mask_token,
                                    const float* __restrict__ g2,
                                    const float* __restrict__ be2,
                                    const float* __restrict__ Wp,
                                    const float* __restrict__ bp)
{
    const int tid = threadIdx.x;
    if (blockIdx.x < 63) {
        const int m = blockIdx.x*256 + tid;
        if (m >= MROWS) return;
        float S1 = 0.f, S2 = 0.f, S3 = 0.f;
        #pragma unroll
        for (int t = 0; t < 8; ++t) {
            S1 += g_part[(0*8 + t)*MROWS + m];
            S2 += g_part[(1*8 + t)*MROWS + m];
            S3 += g_part[(2*8 + t)*MROWS + m];
        }
        const float mean = S1 * (1.0f/DIM);
        const float var  = S2 * (1.0f/DIM) - mean*mean;
        const float inv  = rsqrtf(var + LN_EPS);
        g_s[m] = inv*(S3 - mean*g_consts[0]) + g_consts[1];
    } else {
        float v[4];
        #pragma unroll
        for (int i = 0; i < 4; ++i) v[i] = mask_token[tid + i*256];

        __shared__ float red[256];
        float s = v[0]+v[1]+v[2]+v[3];
        red[tid] = s; __syncthreads();
        #pragma unroll
        for (int o = 128; o > 0; o >>= 1) { if (tid < o) red[tid] += red[tid+o]; __syncthreads(); }
        const float mean = red[0] * (1.0f/DIM);
        __syncthreads();
        float sv = 0.f;
        #pragma unroll
        for (int i = 0; i < 4; ++i) { float dv = v[i]-mean; sv += dv*dv; }
        red[tid] = sv; __syncthreads();
        #pragma unroll
        for (int o = 128; o > 0; o >>= 1) { if (tid < o) red[tid] += red[tid+o]; __syncthreads(); }
        const float inv = rsqrtf(red[0]*(1.0f/DIM) + LN_EPS);
        __syncthreads();
        float part = 0.f;
        #pragma unroll
        for (int i = 0; i < 4; ++i) {
            int d = tid + i*256;
            part += ((v[i]-mean)*inv*g2[d] + be2[d]) * Wp[d];
        }
        red[tid] = part; __syncthreads();
        #pragma unroll
        for (int o = 128; o > 0; o >>= 1) { if (tid < o) red[tid] += red[tid+o]; __syncthreads(); }
        if (tid == 0) g_s[MROWS] = red[0] + bp[0];
    }
}

// ===== Kernel 5: scatter pred/mask + per-batch loss partial =====
__global__ void out_kernel(const float* __restrict__ expr,
                           float* __restrict__ out_pred,
                           float* __restrict__ out_mask)
{
    const int b = blockIdx.x;
    const float cm = g_s[MROWS];
    float part = 0.f;
    for (int l = threadIdx.x; l < LSEQ; l += blockDim.x) {
        const int r = g_rank[b*LSEQ + l];
        const bool masked = (r >= KEEP);
        const float p = masked ? cm : g_s[b*KEEP + r];
        out_pred[b*LSEQ + l] = p;
        out_mask[b*LSEQ + l] = masked ? 1.0f : 0.0f;
        if (masked) {
            float t = expr[b*LSEQ + l];
            if (isnan(t)) t = 0.f;
            const float d = p - t;
            part += d*d;
        }
    }
    __shared__ float red[256];
    red[threadIdx.x] = part; __syncthreads();
    #pragma unroll
    for (int o = 128; o > 0; o >>= 1) {
        if (threadIdx.x < o) red[threadIdx.x] += red[threadIdx.x+o];
        __syncthreads();
    }
    if (threadIdx.x == 0) g_losspart[b] = red[0];
}

// ===== Kernel 6: final loss =====
__global__ void loss_kernel(float* __restrict__ out)
{
    if (threadIdx.x == 0) {
        float s = 0.f;
        for (int i = 0; i < BATCH; ++i) s += g_losspart[i];
        out[0] = s / (float)NMASK;
    }
}

// =============================== launch ===============================
extern "C" void kernel_launch(void* const* d_in, const int* in_sizes, int n_in,
                              void* d_out, int out_size)
{
    const float* expr      = (const float*)d_in[0];
    const int*   idx       = (const int*)  d_in[1];
    const float* noise     = (const float*)d_in[2];
    const float* pos_table = (const float*)d_in[3];
    const float* cls_token = (const float*)d_in[4];
    const float* w_enc     = (const float*)d_in[5];
    const float* b_enc     = (const float*)d_in[6];
    const float* gamma1    = (const float*)d_in[7];
    const float* beta1     = (const float*)d_in[8];
    const float* W_dec     = (const float*)d_in[9];
    const float* b_dec     = (const float*)d_in[10];
    const float* mask_tok  = (const float*)d_in[11];
    const float* gamma2    = (const float*)d_in[12];
    const float* beta2     = (const float*)d_in[13];
    const float* W_pred    = (const float*)d_in[14];
    const float* b_pred    = (const float*)d_in[15];

    float* out = (float*)d_out;
    float* out_loss  = out;
    float* out_pred  = out + 1;
    float* out_mask  = out + 1 + BATCH*LSEQ;
    float* out_lat0  = out + 1 + 2*BATCH*LSEQ;

    cudaFuncSetAttribute(gemm_tc_kernel,
                         cudaFuncAttributeMaxDynamicSharedMemorySize, SMEM_TOTAL);

    setup_kernel<<<1281, 256>>>(noise, W_dec, gamma2, beta2, W_pred, b_pred);
    enc_ln_kernel<<<(BATCH*(KEEP+1))/8, 256>>>(expr, idx, pos_table, cls_token,
                                               w_enc, b_enc, gamma1, beta1, out_lat0);
    gemm_tc_kernel<<<GEMM_GRID, 128, SMEM_TOTAL>>>(b_dec);
    combine_mask_kernel<<<64, 256>>>(mask_tok, gamma2, beta2, W_pred, b_pred);
    out_kernel<<<BATCH, 256>>>(expr, out_pred, out_mask);
    loss_kernel<<<1, 32>>>(out_loss);
}

// round 10
// speedup vs baseline: 1.5430x; 1.3639x over previous
#include <cuda_runtime.h>
#include <cuda_fp16.h>
#include <math.h>
#include <stdint.h>

#define BATCH 32
#define LSEQ  2000
#define DIM   1024
#define KEEP  500
#define MROWS (BATCH*KEEP)           // 16000
#define NMASK (BATCH*(LSEQ-KEEP))    // 48000
#define LN_EPS 1e-5f
#define BSCALE 64.0f
#define INV_BSCALE 0.015625f

// GEMM tiling: CTA 128x128, 4 warps of 64x64, KC=32, 2 stages, 2 CTAs/SM
// fp16 2-product split: D = Ah*Bh + Ah*Bl  (B pre-scaled by 64)
#define MT 128
#define NT 128
#define KC 32
#define NSTAGE (DIM/KC)              // 32
#define NTILES ((MROWS/MT)*(DIM/NT)) // 1000
#define ROWB 80                      // padded smem row bytes
#define SPLIT_B (128*ROWB)           // 10240
#define STAGE_B (3*SPLIT_B)          // 30720 (Ah,Bh,Bl)
#define SMEM_TOTAL (2*STAGE_B)       // 61440
#define GEMM_GRID 296                // persistent

// -------- scratch (device globals) --------
__device__ int   g_rank[BATCH*LSEQ];
__device__ int   g_keep[BATCH*KEEP];
__device__ __align__(16) __half g_Ah[MROWS*DIM];
__device__ __align__(16) __half g_Bh[DIM*DIM];   // [n][k] = 64*W_dec[k][n] hi
__device__ __align__(16) __half g_Bl[DIM*DIM];   // lo residue
__device__ __align__(16) float g_gw[DIM];        // gamma2*W_pred
__device__ float g_consts[2];                    // {sum(g2*Wp), sum(be2*Wp)+bp}
__device__ float g_part[3*8*MROWS];              // [stat][ntile][row]
__device__ float g_s[MROWS+1];
__device__ float g_losspart[BATCH];

// =============================== PTX helpers ===============================
__device__ __forceinline__ uint32_t s2u(const void* p) {
    uint32_t a;
    asm("{ .reg .u64 t; cvta.to.shared.u64 t, %1; cvt.u32.u64 %0, t; }" : "=r"(a) : "l"(p));
    return a;
}
__device__ __forceinline__ void cp16(uint32_t s, const void* g) {
    asm volatile("cp.async.cg.shared.global [%0], [%1], 16;" :: "r"(s), "l"(g) : "memory");
}
__device__ __forceinline__ void ldm4(uint32_t* r, uint32_t addr) {
    asm volatile("ldmatrix.sync.aligned.m8n8.x4.shared.b16 {%0,%1,%2,%3}, [%4];"
                 : "=r"(r[0]), "=r"(r[1]), "=r"(r[2]), "=r"(r[3]) : "r"(addr));
}
__device__ __forceinline__ void mma16816(float* c, const uint32_t* a, const uint32_t* b) {
    asm volatile(
        "mma.sync.aligned.m16n8k16.row.col.f32.f16.f16.f32 "
        "{%0,%1,%2,%3}, {%4,%5,%6,%7}, {%8,%9}, {%0,%1,%2,%3};"
        : "+f"(c[0]), "+f"(c[1]), "+f"(c[2]), "+f"(c[3])
        : "r"(a[0]), "r"(a[1]), "r"(a[2]), "r"(a[3]), "r"(b[0]), "r"(b[1]));
}

// ===== Kernel 1 (fused setup): rank (256 blocks) + prep_b (1024) + consts (1) =====
__global__ void setup_kernel(const float* __restrict__ noise,
                             const float* __restrict__ Wd,
                             const float* __restrict__ g2,
                             const float* __restrict__ be2,
                             const float* __restrict__ Wp,
                             const float* __restrict__ bp)
{
    __shared__ float sh[LSEQ];
    const int bid = blockIdx.x, tid = threadIdx.x;

    if (bid < 256) {
        const int b = bid >> 3, seg = bid & 7;
        const float* nrow = noise + b*LSEQ;
        for (int i = tid; i < LSEQ; i += 256) sh[i] = nrow[i];
        __syncthreads();
        const int j = seg*250 + tid;
        if (tid >= 250) return;
        const float nj = sh[j];
        int r = 0;
        #pragma unroll 4
        for (int k = 0; k < LSEQ; ++k) {
            float nk = sh[k];
            r += (nk < nj) || (nk == nj && k < j);
        }
        g_rank[b*LSEQ + j] = r;
        if (r < KEEP) g_keep[b*KEEP + r] = j;
    } else if (bid < 1280) {
        const int bb = bid - 256, bx = bb & 31, by = bb >> 5;
        float (*t)[33] = (float(*)[33])sh;
        const int tx = tid & 31, ty = tid >> 5;
        #pragma unroll
        for (int j = 0; j < 32; j += 8)
            t[ty+j][tx] = Wd[(size_t)(by*32 + ty + j)*DIM + bx*32 + tx];
        __syncthreads();
        #pragma unroll
        for (int j = 0; j < 32; j += 8) {
            float v = t[tx][ty+j] * BSCALE;
            size_t o = (size_t)(bx*32 + ty + j)*DIM + by*32 + tx;  // [n][k]
            __half h = __float2half_rn(v);
            g_Bh[o] = h;
            g_Bl[o] = __float2half_rn(v - __half2float(h));
        }
    } else {
        float sg = 0.f, sb = 0.f;
        #pragma unroll
        for (int i = 0; i < 4; ++i) {
            int d = tid + i*256;
            float w = Wp[d];
            float gv = g2[d]*w;
            g_gw[d] = gv;
            sg += gv;
            sb += be2[d]*w;
        }
        float* r1 = sh; float* r2 = sh + 256;
        r1[tid] = sg; r2[tid] = sb; __syncthreads();
        #pragma unroll
        for (int o = 128; o > 0; o >>= 1) {
            if (tid < o) { r1[tid] += r1[tid+o]; r2[tid] += r2[tid+o]; }
            __syncthreads();
        }
        if (tid == 0) { g_consts[0] = r1[0]; g_consts[1] = r2[0] + bp[0]; }
    }
}

// ===== Kernel 2: gather + encode + LN1 -> fp16 A (+latent0), warp/row =====
__global__ void enc_ln_kernel(const float* __restrict__ expr,
                              const int*   __restrict__ idx,
                              const float* __restrict__ pos,
                              const float* __restrict__ cls,
                              const float* __restrict__ w_enc,
                              const float* __restrict__ b_enc,
                              const float* __restrict__ g1,
                              const float* __restrict__ be1,
                              float* __restrict__ out_lat0)
{
    const int g = blockIdx.x*8 + (threadIdx.x >> 5);   // 0..16031
    const int lane = threadIdx.x & 31;
    const int b = g / (KEEP+1);
    const int tt = g - b*(KEEP+1);                     // 0 = cls row

    float4 v[8];
    if (tt == 0) {
        #pragma unroll
        for (int i = 0; i < 8; ++i) {
            const int e4 = lane + i*32;
            float4 c = ((const float4*)cls)[e4];
            float4 p = ((const float4*)pos)[e4];
            v[i].x = c.x + p.x; v[i].y = c.y + p.y;
            v[i].z = c.z + p.z; v[i].w = c.w + p.w;
        }
    } else {
        const int j = g_keep[b*KEEP + tt - 1];
        const float e = expr[b*LSEQ + j];
        const float* prow = pos + (size_t)idx[b*LSEQ + j]*DIM;
        #pragma unroll
        for (int i = 0; i < 8; ++i) {
            const int e4 = lane + i*32;
            float4 p  = ((const float4*)prow)[e4];
            float4 w  = ((const float4*)w_enc)[e4];
            float4 bb = ((const float4*)b_enc)[e4];
            v[i].x = fmaf(e, w.x, bb.x) + p.x;
            v[i].y = fmaf(e, w.y, bb.y) + p.y;
            v[i].z = fmaf(e, w.z, bb.z) + p.z;
            v[i].w = fmaf(e, w.w, bb.w) + p.w;
        }
    }

    float s = 0.f, sq = 0.f;
    #pragma unroll
    for (int i = 0; i < 8; ++i) {
        s  += v[i].x + v[i].y + v[i].z + v[i].w;
        sq += v[i].x*v[i].x + v[i].y*v[i].y + v[i].z*v[i].z + v[i].w*v[i].w;
    }
    #pragma unroll
    for (int o = 16; o; o >>= 1) {
        s  += __shfl_xor_sync(0xFFFFFFFFu, s,  o);
        sq += __shfl_xor_sync(0xFFFFFFFFu, sq, o);
    }
    const float mean = s * (1.0f/DIM);
    const float var  = sq * (1.0f/DIM) - mean*mean;
    const float inv  = rsqrtf(var + LN_EPS);

    if (tt == 0) {
        float* dst = out_lat0 + b*DIM;
        #pragma unroll
        for (int i = 0; i < 8; ++i) {
            const int e4 = lane + i*32;
            const float4 gg = ((const float4*)g1)[e4];
            const float4 be = ((const float4*)be1)[e4];
            dst[e4*4+0] = (v[i].x - mean)*inv*gg.x + be.x;
            dst[e4*4+1] = (v[i].y - mean)*inv*gg.y + be.y;
            dst[e4*4+2] = (v[i].z - mean)*inv*gg.z + be.z;
            dst[e4*4+3] = (v[i].w - mean)*inv*gg.w + be.w;
        }
    } else {
        const size_t row = (size_t)(b*KEEP + tt - 1)*DIM;
        #pragma unroll
        for (int i = 0; i < 8; ++i) {
            const int e4 = lane + i*32;
            const float4 gg = ((const float4*)g1)[e4];
            const float4 be = ((const float4*)be1)[e4];
            float r0 = (v[i].x - mean)*inv*gg.x + be.x;
            float r1 = (v[i].y - mean)*inv*gg.y + be.y;
            float r2 = (v[i].z - mean)*inv*gg.z + be.z;
            float r3 = (v[i].w - mean)*inv*gg.w + be.w;
            ((__half2*)(g_Ah + row))[e4*2+0] = __floats2half2_rn(r0, r1);
            ((__half2*)(g_Ah + row))[e4*2+1] = __floats2half2_rn(r2, r3);
        }
    }
}

// ====== Kernel 3: persistent fp16 2-product GEMM, software-pipelined frags ======
__device__ __forceinline__ void load_stage(uint32_t sb, int stage, int bm, int bn, int tid)
{
    const uint32_t st = sb + (uint32_t)(stage & 1) * STAGE_B;
    const int kbase = stage * KC;
    #pragma unroll
    for (int i = 0; i < 12; ++i) {
        const int id = i*128 + tid;           // 0..1535
        const __half* src;
        uint32_t dst;
        if (id < 512) {                       // A: 128 rows x 4 segs
            const int r = id >> 2, seg = id & 3;
            src = g_Ah + (size_t)(bm + r)*DIM + kbase + seg*8;
            dst = st + (uint32_t)(r*ROWB + seg*16);
        } else {                              // Bh/Bl: 128 rows x 4 segs x 2 splits
            const int t = id - 512;
            const int split = t >> 9, u = t & 511, r = u >> 2, seg = u & 3;
            src = (split ? g_Bl : g_Bh) + (size_t)(bn + r)*DIM + kbase + seg*8;
            dst = st + (uint32_t)(SPLIT_B + split*SPLIT_B + r*ROWB + seg*16);
        }
        cp16(dst, src);
    }
    asm volatile("cp.async.commit_group;" ::: "memory");
}

__global__ void __launch_bounds__(128, 2)
gemm_tc_kernel(const float* __restrict__ bias)
{
    extern __shared__ char sm_[];
    const uint32_t sb = s2u(sm_);
    const int tid = threadIdx.x, wid = tid >> 5, lane = tid & 31;
    const int wm = wid & 1, wn = wid >> 1;     // 2x2 warps of 64x64

    const uint32_t aOff = (uint32_t)((wm*64 + (lane & 15))*ROWB + (lane >> 4)*16);
    const uint32_t bOff = (uint32_t)(SPLIT_B
                       + (wn*64 + (lane & 7) + (lane >> 4)*8)*ROWB
                       + ((lane >> 3) & 1)*16);
    const int c2 = (lane & 3)*2;
    const int r4 = lane >> 2;

    uint32_t Ah[4][4], Bh[4][4], Bl[4][4];

    for (int tile = blockIdx.x; tile < NTILES; tile += GEMM_GRID) {
        const int bn = (tile & 7) * NT;
        const int bm = (tile >> 3) * MT;

        float acc[4][8][4] = {};
        __syncthreads();                 // prior tile's epilogue smem reads done
        load_stage(sb, 0, bm, bn, tid);
        load_stage(sb, 1, bm, bn, tid);
        asm volatile("cp.async.wait_group 1;" ::: "memory");
        __syncthreads();

        // preload ks0 frags of stage 0
        {
            const uint32_t st = sb;
            #pragma unroll
            for (int mi = 0; mi < 4; ++mi)
                ldm4(Ah[mi], st + aOff + (uint32_t)(mi*16*ROWB));
            #pragma unroll
            for (int np = 0; np < 4; ++np) {
                ldm4(Bh[np], st + bOff + (uint32_t)(np*16*ROWB));
                ldm4(Bl[np], st + bOff + (uint32_t)(SPLIT_B + np*16*ROWB));
            }
        }

        for (int s = 0; s < NSTAGE; ++s) {
            const uint32_t st = sb + (uint32_t)(s & 1) * STAGE_B;

            // ---- MMAs for ks0 (frags preloaded) ----
            #pragma unroll
            for (int mi = 0; mi < 4; ++mi)
                #pragma unroll
                for (int ni = 0; ni < 8; ++ni)
                    mma16816(acc[mi][ni], Ah[mi], &Bh[ni>>1][(ni&1)*2]);
            #pragma unroll
            for (int mi = 0; mi < 4; ++mi)
                #pragma unroll
                for (int ni = 0; ni < 8; ++ni)
                    mma16816(acc[mi][ni], Ah[mi], &Bl[ni>>1][(ni&1)*2]);

            // ---- load ks1 frags ----
            #pragma unroll
            for (int mi = 0; mi < 4; ++mi)
                ldm4(Ah[mi], st + aOff + (uint32_t)(mi*16*ROWB) + 32u);
            #pragma unroll
            for (int np = 0; np < 4; ++np) {
                ldm4(Bh[np], st + bOff + (uint32_t)(np*16*ROWB) + 32u);
                ldm4(Bl[np], st + bOff + (uint32_t)(SPLIT_B + np*16*ROWB) + 32u);
            }

            // ---- MMAs for ks1 ----
            #pragma unroll
            for (int mi = 0; mi < 4; ++mi)
                #pragma unroll
                for (int ni = 0; ni < 8; ++ni)
                    mma16816(acc[mi][ni], Ah[mi], &Bh[ni>>1][(ni&1)*2]);
            #pragma unroll
            for (int mi = 0; mi < 4; ++mi)
                #pragma unroll
                for (int ni = 0; ni < 8; ++ni)
                    mma16816(acc[mi][ni], Ah[mi], &Bl[ni>>1][(ni&1)*2]);

            if (s + 1 < NSTAGE) {
                asm volatile("cp.async.wait_group 0;" ::: "memory");
                __syncthreads();
                const uint32_t sn = sb + (uint32_t)((s+1) & 1) * STAGE_B;
                // preload ks0 frags of stage s+1
                #pragma unroll
                for (int mi = 0; mi < 4; ++mi)
                    ldm4(Ah[mi], sn + aOff + (uint32_t)(mi*16*ROWB));
                #pragma unroll
                for (int np = 0; np < 4; ++np) {
                    ldm4(Bh[np], sn + bOff + (uint32_t)(np*16*ROWB));
                    ldm4(Bl[np], sn + bOff + (uint32_t)(SPLIT_B + np*16*ROWB));
                }
                if (s + 2 < NSTAGE) load_stage(sb, s + 2, bm, bn, tid);
            }
        }

        // ---- fused epilogue: per-row partial S1,S2,S3 over this CTA's 128 cols ----
        __syncthreads();
        float* sred = (float*)sm_;             // [2 wn][128 rows][3]

        float st1[4][2] = {}, st2[4][2] = {}, st3[4][2] = {};
        #pragma unroll
        for (int ni = 0; ni < 8; ++ni) {
            const int n = bn + wn*64 + ni*8 + c2;
            const float2 bv = *(const float2*)(bias + n);
            const float2 gv = *(const float2*)(g_gw + n);
            #pragma unroll
            for (int mi = 0; mi < 4; ++mi) {
                float x0 = acc[mi][ni][0]*INV_BSCALE + bv.x;
                float x1 = acc[mi][ni][1]*INV_BSCALE + bv.y;
                float x2 = acc[mi][ni][2]*INV_BSCALE + bv.x;
                float x3 = acc[mi][ni][3]*INV_BSCALE + bv.y;
                st1[mi][0] += x0 + x1;           st1[mi][1] += x2 + x3;
                st2[mi][0] += x0*x0 + x1*x1;     st2[mi][1] += x2*x2 + x3*x3;
                st3[mi][0] += x0*gv.x + x1*gv.y; st3[mi][1] += x2*gv.x + x3*gv.y;
            }
        }
        #pragma unroll
        for (int mi = 0; mi < 4; ++mi)
            #pragma unroll
            for (int h = 0; h < 2; ++h) {
                #pragma unroll
                for (int o = 1; o < 4; o <<= 1) {
                    st1[mi][h] += __shfl_xor_sync(0xFFFFFFFFu, st1[mi][h], o);
                    st2[mi][h] += __shfl_xor_sync(0xFFFFFFFFu, st2[mi][h], o);
                    st3[mi][h] += __shfl_xor_sync(0xFFFFFFFFu, st3[mi][h], o);
                }
            }
        if ((lane & 3) == 0) {
            #pragma unroll
            for (int mi = 0; mi < 4; ++mi)
                #pragma unroll
                for (int h = 0; h < 2; ++h) {
                    const int row = wm*64 + mi*16 + h*8 + r4;
                    float* p = sred + (wn*128 + row)*3;
                    p[0] = st1[mi][h]; p[1] = st2[mi][h]; p[2] = st3[mi][h];
                }
        }
        __syncthreads();
        {
            const int m = bm + tid;
            const int t8 = tile & 7;
            #pragma unroll
            for (int c = 0; c < 3; ++c)
                g_part[(c*8 + t8)*MROWS + m] =
                    sred[(0*128 + tid)*3 + c] + sred[(1*128 + tid)*3 + c];
        }
    }
}

// ===== Kernel 4 (fused): combine partials (blocks 0..62) + mask_token pred (63) =====
__global__ void combine_mask_kernel(const float* __restrict__ mask_token,
                                    const float* __restrict__ g2,
                                    const float* __restrict__ be2,
                                    const float* __restrict__ Wp,
                                    const float* __restrict__ bp)
{
    const int tid = threadIdx.x;
    if (blockIdx.x < 63) {
        const int m = blockIdx.x*256 + tid;
        if (m >= MROWS) return;
        float S1 = 0.f, S2 = 0.f, S3 = 0.f;
        #pragma unroll
        for (int t = 0; t < 8; ++t) {
            S1 += g_part[(0*8 + t)*MROWS + m];
            S2 += g_part[(1*8 + t)*MROWS + m];
            S3 += g_part[(2*8 + t)*MROWS + m];
        }
        const float mean = S1 * (1.0f/DIM);
        const float var  = S2 * (1.0f/DIM) - mean*mean;
        const float inv  = rsqrtf(var + LN_EPS);
        g_s[m] = inv*(S3 - mean*g_consts[0]) + g_consts[1];
    } else {
        float v[4];
        #pragma unroll
        for (int i = 0; i < 4; ++i) v[i] = mask_token[tid + i*256];

        __shared__ float red[256];
        float s = v[0]+v[1]+v[2]+v[3];
        red[tid] = s; __syncthreads();
        #pragma unroll
        for (int o = 128; o > 0; o >>= 1) { if (tid < o) red[tid] += red[tid+o]; __syncthreads(); }
        const float mean = red[0] * (1.0f/DIM);
        __syncthreads();
        float sv = 0.f;
        #pragma unroll
        for (int i = 0; i < 4; ++i) { float dv = v[i]-mean; sv += dv*dv; }
        red[tid] = sv; __syncthreads();
        #pragma unroll
        for (int o = 128; o > 0; o >>= 1) { if (tid < o) red[tid] += red[tid+o]; __syncthreads(); }
        const float inv = rsqrtf(red[0]*(1.0f/DIM) + LN_EPS);
        __syncthreads();
        float part = 0.f;
        #pragma unroll
        for (int i = 0; i < 4; ++i) {
            int d = tid + i*256;
            part += ((v[i]-mean)*inv*g2[d] + be2[d]) * Wp[d];
        }
        red[tid] = part; __syncthreads();
        #pragma unroll
        for (int o = 128; o > 0; o >>= 1) { if (tid < o) red[tid] += red[tid+o]; __syncthreads(); }
        if (tid == 0) g_s[MROWS] = red[0] + bp[0];
    }
}

// ===== Kernel 5: scatter pred/mask + per-batch loss partial =====
__global__ void out_kernel(const float* __restrict__ expr,
                           float* __restrict__ out_pred,
                           float* __restrict__ out_mask)
{
    const int b = blockIdx.x;
    const float cm = g_s[MROWS];
    float part = 0.f;
    for (int l = threadIdx.x; l < LSEQ; l += blockDim.x) {
        const int r = g_rank[b*LSEQ + l];
        const bool masked = (r >= KEEP);
        const float p = masked ? cm : g_s[b*KEEP + r];
        out_pred[b*LSEQ + l] = p;
        out_mask[b*LSEQ + l] = masked ? 1.0f : 0.0f;
        if (masked) {
            float t = expr[b*LSEQ + l];
            if (isnan(t)) t = 0.f;
            const float d = p - t;
            part += d*d;
        }
    }
    __shared__ float red[256];
    red[threadIdx.x] = part; __syncthreads();
    #pragma unroll
    for (int o = 128; o > 0; o >>= 1) {
        if (threadIdx.x < o) red[threadIdx.x] += red[threadIdx.x+o];
        __syncthreads();
    }
    if (threadIdx.x == 0) g_losspart[b] = red[0];
}

// ===== Kernel 6: final loss =====
__global__ void loss_kernel(float* __restrict__ out)
{
    if (threadIdx.x == 0) {
        float s = 0.f;
        for (int i = 0; i < BATCH; ++i) s += g_losspart[i];
        out[0] = s / (float)NMASK;
    }
}

// =============================== launch ===============================
extern "C" void kernel_launch(void* const* d_in, const int* in_sizes, int n_in,
                              void* d_out, int out_size)
{
    const float* expr      = (const float*)d_in[0];
    const int*   idx       = (const int*)  d_in[1];
    const float* noise     = (const float*)d_in[2];
    const float* pos_table = (const float*)d_in[3];
    const float* cls_token = (const float*)d_in[4];
    const float* w_enc     = (const float*)d_in[5];
    const float* b_enc     = (const float*)d_in[6];
    const float* gamma1    = (const float*)d_in[7];
    const float* beta1     = (const float*)d_in[8];
    const float* W_dec     = (const float*)d_in[9];
    const float* b_dec     = (const float*)d_in[10];
    const float* mask_tok  = (const float*)d_in[11];
    const float* gamma2    = (const float*)d_in[12];
    const float* beta2     = (const float*)d_in[13];
    const float* W_pred    = (const float*)d_in[14];
    const float* b_pred    = (const float*)d_in[15];

    float* out = (float*)d_out;
    float* out_loss  = out;
    float* out_pred  = out + 1;
    float* out_mask  = out + 1 + BATCH*LSEQ;
    float* out_lat0  = out + 1 + 2*BATCH*LSEQ;

    cudaFuncSetAttribute(gemm_tc_kernel,
                         cudaFuncAttributeMaxDynamicSharedMemorySize, SMEM_TOTAL);

    setup_kernel<<<1281, 256>>>(noise, W_dec, gamma2, beta2, W_pred, b_pred);
    enc_ln_kernel<<<(BATCH*(KEEP+1))/8, 256>>>(expr, idx, pos_table, cls_token,
                                               w_enc, b_enc, gamma1, beta1, out_lat0);
    gemm_tc_kernel<<<GEMM_GRID, 128, SMEM_TOTAL>>>(b_dec);
    combine_mask_kernel<<<64, 256>>>(mask_tok, gamma2, beta2, W_pred, b_pred);
    out_kernel<<<BATCH, 256>>>(expr, out_pred, out_mask);
    loss_kernel<<<1, 32>>>(out_loss);
}

// round 11
// speedup vs baseline: 2.0253x; 1.3125x over previous
#include <cuda_runtime.h>
#include <cuda_fp16.h>
#include <math.h>
#include <stdint.h>

#define BATCH 32
#define LSEQ  2000
#define DIM   1024
#define KEEP  500
#define MROWS (BATCH*KEEP)           // 16000
#define NMASK (BATCH*(LSEQ-KEEP))    // 48000
#define LN_EPS 1e-5f
#define BSCALE 64.0f
#define INV_BSCALE 0.015625f

// GEMM tiling: CTA 128x128, 4 warps of 64x64, KC=64, 2 stages, 2 CTAs/SM
// single-product fp16: D = Ah*Bh  (B pre-scaled by 64)
#define MT 128
#define NT 128
#define KC 64
#define NSTAGE (DIM/KC)              // 16
#define NTILES ((MROWS/MT)*(DIM/NT)) // 1000
#define ROWB 144                     // 64 halfs (128B) + 16B pad
#define SPL (128*ROWB)               // 18432
#define STAGE_B (2*SPL)              // 36864 (A,B)
#define SMEM_TOTAL (2*STAGE_B)       // 73728
#define GEMM_GRID 296                // persistent

// -------- scratch (device globals) --------
__device__ int   g_rank[BATCH*LSEQ];
__device__ int   g_keep[BATCH*KEEP];
__device__ __align__(16) __half g_Ah[MROWS*DIM];
__device__ __align__(16) __half g_Bh[DIM*DIM];   // [n][k] = 64*W_dec[k][n] (fp16)
__device__ __align__(16) float g_gw[DIM];        // gamma2*W_pred
__device__ float g_consts[2];                    // {sum(g2*Wp), sum(be2*Wp)+bp}
__device__ float g_part[3*8*MROWS];              // [stat][ntile][row]
__device__ float g_s[MROWS+1];
__device__ float g_losspart[BATCH];

// =============================== PTX helpers ===============================
__device__ __forceinline__ uint32_t s2u(const void* p) {
    uint32_t a;
    asm("{ .reg .u64 t; cvta.to.shared.u64 t, %1; cvt.u32.u64 %0, t; }" : "=r"(a) : "l"(p));
    return a;
}
__device__ __forceinline__ void cp16(uint32_t s, const void* g) {
    asm volatile("cp.async.cg.shared.global [%0], [%1], 16;" :: "r"(s), "l"(g) : "memory");
}
__device__ __forceinline__ void ldm4(uint32_t* r, uint32_t addr) {
    asm volatile("ldmatrix.sync.aligned.m8n8.x4.shared.b16 {%0,%1,%2,%3}, [%4];"
                 : "=r"(r[0]), "=r"(r[1]), "=r"(r[2]), "=r"(r[3]) : "r"(addr));
}
__device__ __forceinline__ void mma16816(float* c, const uint32_t* a, const uint32_t* b) {
    asm volatile(
        "mma.sync.aligned.m16n8k16.row.col.f32.f16.f16.f32 "
        "{%0,%1,%2,%3}, {%4,%5,%6,%7}, {%8,%9}, {%0,%1,%2,%3};"
        : "+f"(c[0]), "+f"(c[1]), "+f"(c[2]), "+f"(c[3])
        : "r"(a[0]), "r"(a[1]), "r"(a[2]), "r"(a[3]), "r"(b[0]), "r"(b[1]));
}

// ===== Kernel 1 (fused setup): rank (256 blocks) + prep_b (1024) + consts (1) =====
__global__ void setup_kernel(const float* __restrict__ noise,
                             const float* __restrict__ Wd,
                             const float* __restrict__ g2,
                             const float* __restrict__ be2,
                             const float* __restrict__ Wp,
                             const float* __restrict__ bp)
{
    __shared__ float sh[LSEQ];
    const int bid = blockIdx.x, tid = threadIdx.x;

    if (bid < 256) {
        const int b = bid >> 3, seg = bid & 7;
        const float* nrow = noise + b*LSEQ;
        for (int i = tid; i < LSEQ; i += 256) sh[i] = nrow[i];
        __syncthreads();
        const int j = seg*250 + tid;
        if (tid >= 250) return;
        const float nj = sh[j];
        int r = 0;
        #pragma unroll 4
        for (int k = 0; k < LSEQ; ++k) {
            float nk = sh[k];
            r += (nk < nj) || (nk == nj && k < j);
        }
        g_rank[b*LSEQ + j] = r;
        if (r < KEEP) g_keep[b*KEEP + r] = j;
    } else if (bid < 1280) {
        const int bb = bid - 256, bx = bb & 31, by = bb >> 5;
        float (*t)[33] = (float(*)[33])sh;
        const int tx = tid & 31, ty = tid >> 5;
        #pragma unroll
        for (int j = 0; j < 32; j += 8)
            t[ty+j][tx] = Wd[(size_t)(by*32 + ty + j)*DIM + bx*32 + tx];
        __syncthreads();
        #pragma unroll
        for (int j = 0; j < 32; j += 8) {
            float v = t[tx][ty+j] * BSCALE;
            size_t o = (size_t)(bx*32 + ty + j)*DIM + by*32 + tx;  // [n][k]
            g_Bh[o] = __float2half_rn(v);
        }
    } else {
        float sg = 0.f, sb = 0.f;
        #pragma unroll
        for (int i = 0; i < 4; ++i) {
            int d = tid + i*256;
            float w = Wp[d];
            float gv = g2[d]*w;
            g_gw[d] = gv;
            sg += gv;
            sb += be2[d]*w;
        }
        float* r1 = sh; float* r2 = sh + 256;
        r1[tid] = sg; r2[tid] = sb; __syncthreads();
        #pragma unroll
        for (int o = 128; o > 0; o >>= 1) {
            if (tid < o) { r1[tid] += r1[tid+o]; r2[tid] += r2[tid+o]; }
            __syncthreads();
        }
        if (tid == 0) { g_consts[0] = r1[0]; g_consts[1] = r2[0] + bp[0]; }
    }
}

// ===== Kernel 2: gather + encode + LN1 -> fp16 A (+latent0), warp/row =====
__global__ void enc_ln_kernel(const float* __restrict__ expr,
                              const int*   __restrict__ idx,
                              const float* __restrict__ pos,
                              const float* __restrict__ cls,
                              const float* __restrict__ w_enc,
                              const float* __restrict__ b_enc,
                              const float* __restrict__ g1,
                              const float* __restrict__ be1,
                              float* __restrict__ out_lat0)
{
    const int g = blockIdx.x*8 + (threadIdx.x >> 5);   // 0..16031
    const int lane = threadIdx.x & 31;
    const int b = g / (KEEP+1);
    const int tt = g - b*(KEEP+1);                     // 0 = cls row

    float4 v[8];
    if (tt == 0) {
        #pragma unroll
        for (int i = 0; i < 8; ++i) {
            const int e4 = lane + i*32;
            float4 c = ((const float4*)cls)[e4];
            float4 p = ((const float4*)pos)[e4];
            v[i].x = c.x + p.x; v[i].y = c.y + p.y;
            v[i].z = c.z + p.z; v[i].w = c.w + p.w;
        }
    } else {
        const int j = g_keep[b*KEEP + tt - 1];
        const float e = expr[b*LSEQ + j];
        const float* prow = pos + (size_t)idx[b*LSEQ + j]*DIM;
        #pragma unroll
        for (int i = 0; i < 8; ++i) {
            const int e4 = lane + i*32;
            float4 p  = ((const float4*)prow)[e4];
            float4 w  = ((const float4*)w_enc)[e4];
            float4 bb = ((const float4*)b_enc)[e4];
            v[i].x = fmaf(e, w.x, bb.x) + p.x;
            v[i].y = fmaf(e, w.y, bb.y) + p.y;
            v[i].z = fmaf(e, w.z, bb.z) + p.z;
            v[i].w = fmaf(e, w.w, bb.w) + p.w;
        }
    }

    float s = 0.f, sq = 0.f;
    #pragma unroll
    for (int i = 0; i < 8; ++i) {
        s  += v[i].x + v[i].y + v[i].z + v[i].w;
        sq += v[i].x*v[i].x + v[i].y*v[i].y + v[i].z*v[i].z + v[i].w*v[i].w;
    }
    #pragma unroll
    for (int o = 16; o; o >>= 1) {
        s  += __shfl_xor_sync(0xFFFFFFFFu, s,  o);
        sq += __shfl_xor_sync(0xFFFFFFFFu, sq, o);
    }
    const float mean = s * (1.0f/DIM);
    const float var  = sq * (1.0f/DIM) - mean*mean;
    const float inv  = rsqrtf(var + LN_EPS);

    if (tt == 0) {
        float* dst = out_lat0 + b*DIM;
        #pragma unroll
        for (int i = 0; i < 8; ++i) {
            const int e4 = lane + i*32;
            const float4 gg = ((const float4*)g1)[e4];
            const float4 be = ((const float4*)be1)[e4];
            dst[e4*4+0] = (v[i].x - mean)*inv*gg.x + be.x;
            dst[e4*4+1] = (v[i].y - mean)*inv*gg.y + be.y;
            dst[e4*4+2] = (v[i].z - mean)*inv*gg.z + be.z;
            dst[e4*4+3] = (v[i].w - mean)*inv*gg.w + be.w;
        }
    } else {
        const size_t row = (size_t)(b*KEEP + tt - 1)*DIM;
        #pragma unroll
        for (int i = 0; i < 8; ++i) {
            const int e4 = lane + i*32;
            const float4 gg = ((const float4*)g1)[e4];
            const float4 be = ((const float4*)be1)[e4];
            float r0 = (v[i].x - mean)*inv*gg.x + be.x;
            float r1 = (v[i].y - mean)*inv*gg.y + be.y;
            float r2 = (v[i].z - mean)*inv*gg.z + be.z;
            float r3 = (v[i].w - mean)*inv*gg.w + be.w;
            ((__half2*)(g_Ah + row))[e4*2+0] = __floats2half2_rn(r0, r1);
            ((__half2*)(g_Ah + row))[e4*2+1] = __floats2half2_rn(r2, r3);
        }
    }
}

// ====== Kernel 3: persistent fp16 GEMM, KC=64, software-pipelined frags ======
__device__ __forceinline__ void load_stage(uint32_t sb, int stage, int bm, int bn, int tid)
{
    const uint32_t st = sb + (uint32_t)(stage & 1) * STAGE_B;
    const int kbase = stage * KC;
    #pragma unroll
    for (int i = 0; i < 16; ++i) {
        const int id = i*128 + tid;           // 0..2047
        const __half* src;
        uint32_t dst;
        if (id < 1024) {                      // A: 128 rows x 8 segs
            const int r = id >> 3, seg = id & 7;
            src = g_Ah + (size_t)(bm + r)*DIM + kbase + seg*8;
            dst = st + (uint32_t)(r*ROWB + seg*16);
        } else {                              // B: 128 rows x 8 segs
            const int t = id - 1024;
            const int r = t >> 3, seg = t & 7;
            src = g_Bh + (size_t)(bn + r)*DIM + kbase + seg*8;
            dst = st + (uint32_t)(SPL + r*ROWB + seg*16);
        }
        cp16(dst, src);
    }
    asm volatile("cp.async.commit_group;" ::: "memory");
}

__global__ void __launch_bounds__(128, 2)
gemm_tc_kernel(const float* __restrict__ bias)
{
    extern __shared__ char sm_[];
    const uint32_t sb = s2u(sm_);
    const int tid = threadIdx.x, wid = tid >> 5, lane = tid & 31;
    const int wm = wid & 1, wn = wid >> 1;     // 2x2 warps of 64x64

    const uint32_t aOff = (uint32_t)((wm*64 + (lane & 15))*ROWB + (lane >> 4)*16);
    const uint32_t bOff = (uint32_t)(SPL
                       + (wn*64 + (lane & 7) + (lane >> 4)*8)*ROWB
                       + ((lane >> 3) & 1)*16);
    const int c2 = (lane & 3)*2;
    const int r4 = lane >> 2;

    uint32_t Ah[4][4], Bh[4][4];

    for (int tile = blockIdx.x; tile < NTILES; tile += GEMM_GRID) {
        const int bn = (tile & 7) * NT;
        const int bm = (tile >> 3) * MT;

        float acc[4][8][4] = {};
        __syncthreads();                 // prior tile's epilogue smem reads done
        load_stage(sb, 0, bm, bn, tid);
        load_stage(sb, 1, bm, bn, tid);
        asm volatile("cp.async.wait_group 1;" ::: "memory");
        __syncthreads();

        // preload ks0 frags of stage 0
        #pragma unroll
        for (int mi = 0; mi < 4; ++mi)
            ldm4(Ah[mi], sb + aOff + (uint32_t)(mi*16*ROWB));
        #pragma unroll
        for (int np = 0; np < 4; ++np)
            ldm4(Bh[np], sb + bOff + (uint32_t)(np*16*ROWB));

        for (int s = 0; s < NSTAGE; ++s) {
            const uint32_t st = sb + (uint32_t)(s & 1) * STAGE_B;

            // ks = 0..2: MMA with current frags, then load next ks frags
            #pragma unroll
            for (int ks = 0; ks < 3; ++ks) {
                #pragma unroll
                for (int mi = 0; mi < 4; ++mi)
                    #pragma unroll
                    for (int ni = 0; ni < 8; ++ni)
                        mma16816(acc[mi][ni], Ah[mi], &Bh[ni>>1][(ni&1)*2]);
                const uint32_t kb = (uint32_t)((ks+1)*32);
                #pragma unroll
                for (int mi = 0; mi < 4; ++mi)
                    ldm4(Ah[mi], st + aOff + (uint32_t)(mi*16*ROWB) + kb);
                #pragma unroll
                for (int np = 0; np < 4; ++np)
                    ldm4(Bh[np], st + bOff + (uint32_t)(np*16*ROWB) + kb);
            }
            // ks = 3
            #pragma unroll
            for (int mi = 0; mi < 4; ++mi)
                #pragma unroll
                for (int ni = 0; ni < 8; ++ni)
                    mma16816(acc[mi][ni], Ah[mi], &Bh[ni>>1][(ni&1)*2]);

            if (s + 1 < NSTAGE) {
                asm volatile("cp.async.wait_group 0;" ::: "memory");
                __syncthreads();
                const uint32_t sn = sb + (uint32_t)((s+1) & 1) * STAGE_B;
                // preload ks0 frags of stage s+1
                #pragma unroll
                for (int mi = 0; mi < 4; ++mi)
                    ldm4(Ah[mi], sn + aOff + (uint32_t)(mi*16*ROWB));
                #pragma unroll
                for (int np = 0; np < 4; ++np)
                    ldm4(Bh[np], sn + bOff + (uint32_t)(np*16*ROWB));
                if (s + 2 < NSTAGE) load_stage(sb, s + 2, bm, bn, tid);
            }
        }

        // ---- fused epilogue: per-row partial S1,S2,S3 over this CTA's 128 cols ----
        __syncthreads();
        float* sred = (float*)sm_;             // [2 wn][128 rows][3]

        float st1[4][2] = {}, st2[4][2] = {}, st3[4][2] = {};
        #pragma unroll
        for (int ni = 0; ni < 8; ++ni) {
            const int n = bn + wn*64 + ni*8 + c2;
            const float2 bv = *(const float2*)(bias + n);
            const float2 gv = *(const float2*)(g_gw + n);
            #pragma unroll
            for (int mi = 0; mi < 4; ++mi) {
                float x0 = acc[mi][ni][0]*INV_BSCALE + bv.x;
                float x1 = acc[mi][ni][1]*INV_BSCALE + bv.y;
                float x2 = acc[mi][ni][2]*INV_BSCALE + bv.x;
                float x3 = acc[mi][ni][3]*INV_BSCALE + bv.y;
                st1[mi][0] += x0 + x1;           st1[mi][1] += x2 + x3;
                st2[mi][0] += x0*x0 + x1*x1;     st2[mi][1] += x2*x2 + x3*x3;
                st3[mi][0] += x0*gv.x + x1*gv.y; st3[mi][1] += x2*gv.x + x3*gv.y;
            }
        }
        #pragma unroll
        for (int mi = 0; mi < 4; ++mi)
            #pragma unroll
            for (int h = 0; h < 2; ++h) {
                #pragma unroll
                for (int o = 1; o < 4; o <<= 1) {
                    st1[mi][h] += __shfl_xor_sync(0xFFFFFFFFu, st1[mi][h], o);
                    st2[mi][h] += __shfl_xor_sync(0xFFFFFFFFu, st2[mi][h], o);
                    st3[mi][h] += __shfl_xor_sync(0xFFFFFFFFu, st3[mi][h], o);
                }
            }
        if ((lane & 3) == 0) {
            #pragma unroll
            for (int mi = 0; mi < 4; ++mi)
                #pragma unroll
                for (int h = 0; h < 2; ++h) {
                    const int row = wm*64 + mi*16 + h*8 + r4;
                    float* p = sred + (wn*128 + row)*3;
                    p[0] = st1[mi][h]; p[1] = st2[mi][h]; p[2] = st3[mi][h];
                }
        }
        __syncthreads();
        {
            const int m = bm + tid;
            const int t8 = tile & 7;
            #pragma unroll
            for (int c = 0; c < 3; ++c)
                g_part[(c*8 + t8)*MROWS + m] =
                    sred[(0*128 + tid)*3 + c] + sred[(1*128 + tid)*3 + c];
        }
    }
}

// ===== Kernel 4 (fused): combine partials (blocks 0..62) + mask_token pred (63) =====
__global__ void combine_mask_kernel(const float* __restrict__ mask_token,
                                    const float* __restrict__ g2,
                                    const float* __restrict__ be2,
                                    const float* __restrict__ Wp,
                                    const float* __restrict__ bp)
{
    const int tid = threadIdx.x;
    if (blockIdx.x < 63) {
        const int m = blockIdx.x*256 + tid;
        if (m >= MROWS) return;
        float S1 = 0.f, S2 = 0.f, S3 = 0.f;
        #pragma unroll
        for (int t = 0; t < 8; ++t) {
            S1 += g_part[(0*8 + t)*MROWS + m];
            S2 += g_part[(1*8 + t)*MROWS + m];
            S3 += g_part[(2*8 + t)*MROWS + m];
        }
        const float mean = S1 * (1.0f/DIM);
        const float var  = S2 * (1.0f/DIM) - mean*mean;
        const float inv  = rsqrtf(var + LN_EPS);
        g_s[m] = inv*(S3 - mean*g_consts[0]) + g_consts[1];
    } else {
        float v[4];
        #pragma unroll
        for (int i = 0; i < 4; ++i) v[i] = mask_token[tid + i*256];

        __shared__ float red[256];
        float s = v[0]+v[1]+v[2]+v[3];
        red[tid] = s; __syncthreads();
        #pragma unroll
        for (int o = 128; o > 0; o >>= 1) { if (tid < o) red[tid] += red[tid+o]; __syncthreads(); }
        const float mean = red[0] * (1.0f/DIM);
        __syncthreads();
        float sv = 0.f;
        #pragma unroll
        for (int i = 0; i < 4; ++i) { float dv = v[i]-mean; sv += dv*dv; }
        red[tid] = sv; __syncthreads();
        #pragma unroll
        for (int o = 128; o > 0; o >>= 1) { if (tid < o) red[tid] += red[tid+o]; __syncthreads(); }
        const float inv = rsqrtf(red[0]*(1.0f/DIM) + LN_EPS);
        __syncthreads();
        float part = 0.f;
        #pragma unroll
        for (int i = 0; i < 4; ++i) {
            int d = tid + i*256;
            part += ((v[i]-mean)*inv*g2[d] + be2[d]) * Wp[d];
        }
        red[tid] = part; __syncthreads();
        #pragma unroll
        for (int o = 128; o > 0; o >>= 1) { if (tid < o) red[tid] += red[tid+o]; __syncthreads(); }
        if (tid == 0) g_s[MROWS] = red[0] + bp[0];
    }
}

// ===== Kernel 5: scatter pred/mask + per-batch loss partial =====
__global__ void out_kernel(const float* __restrict__ expr,
                           float* __restrict__ out_pred,
                           float* __restrict__ out_mask)
{
    const int b = blockIdx.x;
    const float cm = g_s[MROWS];
    float part = 0.f;
    for (int l = threadIdx.x; l < LSEQ; l += blockDim.x) {
        const int r = g_rank[b*LSEQ + l];
        const bool masked = (r >= KEEP);
        const float p = masked ? cm : g_s[b*KEEP + r];
        out_pred[b*LSEQ + l] = p;
        out_mask[b*LSEQ + l] = masked ? 1.0f : 0.0f;
        if (masked) {
            float t = expr[b*LSEQ + l];
            if (isnan(t)) t = 0.f;
            const float d = p - t;
            part += d*d;
        }
    }
    __shared__ float red[256];
    red[threadIdx.x] = part; __syncthreads();
    #pragma unroll
    for (int o = 128; o > 0; o >>= 1) {
        if (threadIdx.x < o) red[threadIdx.x] += red[threadIdx.x+o];
        __syncthreads();
    }
    if (threadIdx.x == 0) g_losspart[b] = red[0];
}

// ===== Kernel 6: final loss =====
__global__ void loss_kernel(float* __restrict__ out)
{
    if (threadIdx.x == 0) {
        float s = 0.f;
        for (int i = 0; i < BATCH; ++i) s += g_losspart[i];
        out[0] = s / (float)NMASK;
    }
}

// =============================== launch ===============================
extern "C" void kernel_launch(void* const* d_in, const int* in_sizes, int n_in,
                              void* d_out, int out_size)
{
    const float* expr      = (const float*)d_in[0];
    const int*   idx       = (const int*)  d_in[1];
    const float* noise     = (const float*)d_in[2];
    const float* pos_table = (const float*)d_in[3];
    const float* cls_token = (const float*)d_in[4];
    const float* w_enc     = (const float*)d_in[5];
    const float* b_enc     = (const float*)d_in[6];
    const float* gamma1    = (const float*)d_in[7];
    const float* beta1     = (const float*)d_in[8];
    const float* W_dec     = (const float*)d_in[9];
    const float* b_dec     = (const float*)d_in[10];
    const float* mask_tok  = (const float*)d_in[11];
    const float* gamma2    = (const float*)d_in[12];
    const float* beta2     = (const float*)d_in[13];
    const float* W_pred    = (const float*)d_in[14];
    const float* b_pred    = (const float*)d_in[15];

    float* out = (float*)d_out;
    float* out_loss  = out;
    float* out_pred  = out + 1;
    float* out_mask  = out + 1 + BATCH*LSEQ;
    float* out_lat0  = out + 1 + 2*BATCH*LSEQ;

    cudaFuncSetAttribute(gemm_tc_kernel,
                         cudaFuncAttributeMaxDynamicSharedMemorySize, SMEM_TOTAL);

    setup_kernel<<<1281, 256>>>(noise, W_dec, gamma2, beta2, W_pred, b_pred);
    enc_ln_kernel<<<(BATCH*(KEEP+1))/8, 256>>>(expr, idx, pos_table, cls_token,
                                               w_enc, b_enc, gamma1, beta1, out_lat0);
    gemm_tc_kernel<<<GEMM_GRID, 128, SMEM_TOTAL>>>(b_dec);
    combine_mask_kernel<<<64, 256>>>(mask_tok, gamma2, beta2, W_pred, b_pred);
    out_kernel<<<BATCH, 256>>>(expr, out_pred, out_mask);
    loss_kernel<<<1, 32>>>(out_loss);
}

// round 12
// speedup vs baseline: 2.0488x; 1.0116x over previous
#include <cuda_runtime.h>
#include <cuda_fp16.h>
#include <math.h>
#include <stdint.h>

#define BATCH 32
#define LSEQ  2000
#define DIM   1024
#define KEEP  500
#define MROWS (BATCH*KEEP)           // 16000
#define NMASK (BATCH*(LSEQ-KEEP))    // 48000
#define LN_EPS 1e-5f
#define BSCALE 64.0f
#define INV_BSCALE 0.015625f

// GEMM tiling: CTA 128x128, 4 warps of 64x64, KC=64, 3 stages, 2 CTAs/SM
#define MT 128
#define NT 128
#define KC 64
#define NSTAGE (DIM/KC)              // 16
#define NTILES ((MROWS/MT)*(DIM/NT)) // 1000
#define ROWB 144                     // 64 halfs (128B) + 16B pad
#define SPL (128*ROWB)               // 18432
#define STAGE_B (2*SPL)              // 36864 (A,B)
#define SMEM_TOTAL (3*STAGE_B)       // 110592
#define GEMM_GRID 296                // persistent

// -------- scratch (device globals) --------
__device__ int   g_rank[BATCH*LSEQ];
__device__ int   g_keep[BATCH*KEEP];
__device__ __align__(16) __half g_Ah[MROWS*DIM];
__device__ __align__(16) __half g_Bh[DIM*DIM];   // [n][k] = 64*W_dec[k][n] (fp16)
__device__ __align__(16) float g_gw[DIM];        // gamma2*W_pred
__device__ float g_consts[2];                    // {sum(g2*Wp), sum(be2*Wp)+bp}
__device__ float g_part[3*8*MROWS];              // [stat][ntile][row]
__device__ float g_losspart[BATCH];

// =============================== PTX helpers ===============================
__device__ __forceinline__ uint32_t s2u(const void* p) {
    uint32_t a;
    asm("{ .reg .u64 t; cvta.to.shared.u64 t, %1; cvt.u32.u64 %0, t; }" : "=r"(a) : "l"(p));
    return a;
}
__device__ __forceinline__ void cp16(uint32_t s, const void* g) {
    asm volatile("cp.async.cg.shared.global [%0], [%1], 16;" :: "r"(s), "l"(g) : "memory");
}
__device__ __forceinline__ void ldm4(uint32_t* r, uint32_t addr) {
    asm volatile("ldmatrix.sync.aligned.m8n8.x4.shared.b16 {%0,%1,%2,%3}, [%4];"
                 : "=r"(r[0]), "=r"(r[1]), "=r"(r[2]), "=r"(r[3]) : "r"(addr));
}
__device__ __forceinline__ void mma16816(float* c, const uint32_t* a, const uint32_t* b) {
    asm volatile(
        "mma.sync.aligned.m16n8k16.row.col.f32.f16.f16.f32 "
        "{%0,%1,%2,%3}, {%4,%5,%6,%7}, {%8,%9}, {%0,%1,%2,%3};"
        : "+f"(c[0]), "+f"(c[1]), "+f"(c[2]), "+f"(c[3])
        : "r"(a[0]), "r"(a[1]), "r"(a[2]), "r"(a[3]), "r"(b[0]), "r"(b[1]));
}

// ===== Kernel 1 (fused setup): rank (256 blocks) + prep_b (1024) + consts (1) =====
__global__ void setup_kernel(const float* __restrict__ noise,
                             const float* __restrict__ Wd,
                             const float* __restrict__ g2,
                             const float* __restrict__ be2,
                             const float* __restrict__ Wp,
                             const float* __restrict__ bp)
{
    __shared__ float sh[LSEQ];
    const int bid = blockIdx.x, tid = threadIdx.x;

    if (bid < 256) {
        const int b = bid >> 3, seg = bid & 7;
        const float* nrow = noise + b*LSEQ;
        for (int i = tid; i < LSEQ; i += 256) sh[i] = nrow[i];
        __syncthreads();
        const int j = seg*250 + tid;
        if (tid >= 250) return;
        const float nj = sh[j];
        int r = 0;
        #pragma unroll 4
        for (int k = 0; k < LSEQ; ++k) {
            float nk = sh[k];
            r += (nk < nj) || (nk == nj && k < j);
        }
        g_rank[b*LSEQ + j] = r;
        if (r < KEEP) g_keep[b*KEEP + r] = j;
    } else if (bid < 1280) {
        const int bb = bid - 256, bx = bb & 31, by = bb >> 5;
        float (*t)[33] = (float(*)[33])sh;
        const int tx = tid & 31, ty = tid >> 5;
        #pragma unroll
        for (int j = 0; j < 32; j += 8)
            t[ty+j][tx] = Wd[(size_t)(by*32 + ty + j)*DIM + bx*32 + tx];
        __syncthreads();
        #pragma unroll
        for (int j = 0; j < 32; j += 8) {
            float v = t[tx][ty+j] * BSCALE;
            size_t o = (size_t)(bx*32 + ty + j)*DIM + by*32 + tx;  // [n][k]
            g_Bh[o] = __float2half_rn(v);
        }
    } else {
        float sg = 0.f, sb = 0.f;
        #pragma unroll
        for (int i = 0; i < 4; ++i) {
            int d = tid + i*256;
            float w = Wp[d];
            float gv = g2[d]*w;
            g_gw[d] = gv;
            sg += gv;
            sb += be2[d]*w;
        }
        float* r1 = sh; float* r2 = sh + 256;
        r1[tid] = sg; r2[tid] = sb; __syncthreads();
        #pragma unroll
        for (int o = 128; o > 0; o >>= 1) {
            if (tid < o) { r1[tid] += r1[tid+o]; r2[tid] += r2[tid+o]; }
            __syncthreads();
        }
        if (tid == 0) { g_consts[0] = r1[0]; g_consts[1] = r2[0] + bp[0]; }
    }
}

// ===== Kernel 2: gather + encode + LN1 -> fp16 A (+latent0), warp/row =====
__global__ void enc_ln_kernel(const float* __restrict__ expr,
                              const int*   __restrict__ idx,
                              const float* __restrict__ pos,
                              const float* __restrict__ cls,
                              const float* __restrict__ w_enc,
                              const float* __restrict__ b_enc,
                              const float* __restrict__ g1,
                              const float* __restrict__ be1,
                              float* __restrict__ out_lat0)
{
    const int g = blockIdx.x*8 + (threadIdx.x >> 5);   // 0..16031
    const int lane = threadIdx.x & 31;
    const int b = g / (KEEP+1);
    const int tt = g - b*(KEEP+1);                     // 0 = cls row

    float4 v[8];
    if (tt == 0) {
        #pragma unroll
        for (int i = 0; i < 8; ++i) {
            const int e4 = lane + i*32;
            float4 c = ((const float4*)cls)[e4];
            float4 p = ((const float4*)pos)[e4];
            v[i].x = c.x + p.x; v[i].y = c.y + p.y;
            v[i].z = c.z + p.z; v[i].w = c.w + p.w;
        }
    } else {
        const int j = g_keep[b*KEEP + tt - 1];
        const float e = expr[b*LSEQ + j];
        const float* prow = pos + (size_t)idx[b*LSEQ + j]*DIM;
        #pragma unroll
        for (int i = 0; i < 8; ++i) {
            const int e4 = lane + i*32;
            float4 p  = ((const float4*)prow)[e4];
            float4 w  = ((const float4*)w_enc)[e4];
            float4 bb = ((const float4*)b_enc)[e4];
            v[i].x = fmaf(e, w.x, bb.x) + p.x;
            v[i].y = fmaf(e, w.y, bb.y) + p.y;
            v[i].z = fmaf(e, w.z, bb.z) + p.z;
            v[i].w = fmaf(e, w.w, bb.w) + p.w;
        }
    }

    float s = 0.f, sq = 0.f;
    #pragma unroll
    for (int i = 0; i < 8; ++i) {
        s  += v[i].x + v[i].y + v[i].z + v[i].w;
        sq += v[i].x*v[i].x + v[i].y*v[i].y + v[i].z*v[i].z + v[i].w*v[i].w;
    }
    #pragma unroll
    for (int o = 16; o; o >>= 1) {
        s  += __shfl_xor_sync(0xFFFFFFFFu, s,  o);
        sq += __shfl_xor_sync(0xFFFFFFFFu, sq, o);
    }
    const float mean = s * (1.0f/DIM);
    const float var  = sq * (1.0f/DIM) - mean*mean;
    const float inv  = rsqrtf(var + LN_EPS);

    if (tt == 0) {
        float* dst = out_lat0 + b*DIM;
        #pragma unroll
        for (int i = 0; i < 8; ++i) {
            const int e4 = lane + i*32;
            const float4 gg = ((const float4*)g1)[e4];
            const float4 be = ((const float4*)be1)[e4];
            dst[e4*4+0] = (v[i].x - mean)*inv*gg.x + be.x;
            dst[e4*4+1] = (v[i].y - mean)*inv*gg.y + be.y;
            dst[e4*4+2] = (v[i].z - mean)*inv*gg.z + be.z;
            dst[e4*4+3] = (v[i].w - mean)*inv*gg.w + be.w;
        }
    } else {
        const size_t row = (size_t)(b*KEEP + tt - 1)*DIM;
        #pragma unroll
        for (int i = 0; i < 8; ++i) {
            const int e4 = lane + i*32;
            const float4 gg = ((const float4*)g1)[e4];
            const float4 be = ((const float4*)be1)[e4];
            float r0 = (v[i].x - mean)*inv*gg.x + be.x;
            float r1 = (v[i].y - mean)*inv*gg.y + be.y;
            float r2 = (v[i].z - mean)*inv*gg.z + be.z;
            float r3 = (v[i].w - mean)*inv*gg.w + be.w;
            ((__half2*)(g_Ah + row))[e4*2+0] = __floats2half2_rn(r0, r1);
            ((__half2*)(g_Ah + row))[e4*2+1] = __floats2half2_rn(r2, r3);
        }
    }
}

// ====== Kernel 3: persistent fp16 GEMM, KC=64, 3-stage, pipelined frags ======
__device__ __forceinline__ void load_stage(uint32_t sb, int stage, int bm, int bn, int tid)
{
    const uint32_t st = sb + (uint32_t)(stage % 3) * STAGE_B;
    const int kbase = stage * KC;
    #pragma unroll
    for (int i = 0; i < 16; ++i) {
        const int id = i*128 + tid;           // 0..2047
        const __half* src;
        uint32_t dst;
        if (id < 1024) {                      // A: 128 rows x 8 segs
            const int r = id >> 3, seg = id & 7;
            src = g_Ah + (size_t)(bm + r)*DIM + kbase + seg*8;
            dst = st + (uint32_t)(r*ROWB + seg*16);
        } else {                              // B: 128 rows x 8 segs
            const int t = id - 1024;
            const int r = t >> 3, seg = t & 7;
            src = g_Bh + (size_t)(bn + r)*DIM + kbase + seg*8;
            dst = st + (uint32_t)(SPL + r*ROWB + seg*16);
        }
        cp16(dst, src);
    }
    asm volatile("cp.async.commit_group;" ::: "memory");
}

__global__ void __launch_bounds__(128, 2)
gemm_tc_kernel(const float* __restrict__ bias)
{
    extern __shared__ char sm_[];
    const uint32_t sb = s2u(sm_);
    const int tid = threadIdx.x, wid = tid >> 5, lane = tid & 31;
    const int wm = wid & 1, wn = wid >> 1;     // 2x2 warps of 64x64

    const uint32_t aOff = (uint32_t)((wm*64 + (lane & 15))*ROWB + (lane >> 4)*16);
    const uint32_t bOff = (uint32_t)(SPL
                       + (wn*64 + (lane & 7) + (lane >> 4)*8)*ROWB
                       + ((lane >> 3) & 1)*16);
    const int c2 = (lane & 3)*2;
    const int r4 = lane >> 2;

    uint32_t Ah[4][4], Bh[4][4];

    for (int tile = blockIdx.x; tile < NTILES; tile += GEMM_GRID) {
        const int bn = (tile & 7) * NT;
        const int bm = (tile >> 3) * MT;

        float acc[4][8][4] = {};
        __syncthreads();                 // prior tile's epilogue smem reads done
        load_stage(sb, 0, bm, bn, tid);
        load_stage(sb, 1, bm, bn, tid);
        load_stage(sb, 2, bm, bn, tid);
        asm volatile("cp.async.wait_group 2;" ::: "memory");
        __syncthreads();

        // preload ks0 frags of stage 0
        #pragma unroll
        for (int mi = 0; mi < 4; ++mi)
            ldm4(Ah[mi], sb + aOff + (uint32_t)(mi*16*ROWB));
        #pragma unroll
        for (int np = 0; np < 4; ++np)
            ldm4(Bh[np], sb + bOff + (uint32_t)(np*16*ROWB));

        for (int s = 0; s < NSTAGE; ++s) {
            const uint32_t st = sb + (uint32_t)(s % 3) * STAGE_B;

            // ks = 0..2: MMA with current frags, then load next ks frags
            #pragma unroll
            for (int ks = 0; ks < 3; ++ks) {
                #pragma unroll
                for (int mi = 0; mi < 4; ++mi)
                    #pragma unroll
                    for (int ni = 0; ni < 8; ++ni)
                        mma16816(acc[mi][ni], Ah[mi], &Bh[ni>>1][(ni&1)*2]);
                const uint32_t kb = (uint32_t)((ks+1)*32);
                #pragma unroll
                for (int mi = 0; mi < 4; ++mi)
                    ldm4(Ah[mi], st + aOff + (uint32_t)(mi*16*ROWB) + kb);
                #pragma unroll
                for (int np = 0; np < 4; ++np)
                    ldm4(Bh[np], st + bOff + (uint32_t)(np*16*ROWB) + kb);
            }
            // ks = 3
            #pragma unroll
            for (int mi = 0; mi < 4; ++mi)
                #pragma unroll
                for (int ni = 0; ni < 8; ++ni)
                    mma16816(acc[mi][ni], Ah[mi], &Bh[ni>>1][(ni&1)*2]);

            if (s + 1 < NSTAGE) {
                if (s + 3 < NSTAGE)
                    asm volatile("cp.async.wait_group 1;" ::: "memory");
                else
                    asm volatile("cp.async.wait_group 0;" ::: "memory");
                __syncthreads();
                const uint32_t sn = sb + (uint32_t)((s+1) % 3) * STAGE_B;
                // preload ks0 frags of stage s+1
                #pragma unroll
                for (int mi = 0; mi < 4; ++mi)
                    ldm4(Ah[mi], sn + aOff + (uint32_t)(mi*16*ROWB));
                #pragma unroll
                for (int np = 0; np < 4; ++np)
                    ldm4(Bh[np], sn + bOff + (uint32_t)(np*16*ROWB));
                if (s + 3 < NSTAGE) load_stage(sb, s + 3, bm, bn, tid);
            }
        }

        // ---- fused epilogue: per-row partial S1,S2,S3 over this CTA's 128 cols ----
        __syncthreads();
        float* sred = (float*)sm_;             // [2 wn][128 rows][3]

        float st1[4][2] = {}, st2[4][2] = {}, st3[4][2] = {};
        #pragma unroll
        for (int ni = 0; ni < 8; ++ni) {
            const int n = bn + wn*64 + ni*8 + c2;
            const float2 bv = *(const float2*)(bias + n);
            const float2 gv = *(const float2*)(g_gw + n);
            #pragma unroll
            for (int mi = 0; mi < 4; ++mi) {
                float x0 = acc[mi][ni][0]*INV_BSCALE + bv.x;
                float x1 = acc[mi][ni][1]*INV_BSCALE + bv.y;
                float x2 = acc[mi][ni][2]*INV_BSCALE + bv.x;
                float x3 = acc[mi][ni][3]*INV_BSCALE + bv.y;
                st1[mi][0] += x0 + x1;           st1[mi][1] += x2 + x3;
                st2[mi][0] += x0*x0 + x1*x1;     st2[mi][1] += x2*x2 + x3*x3;
                st3[mi][0] += x0*gv.x + x1*gv.y; st3[mi][1] += x2*gv.x + x3*gv.y;
            }
        }
        #pragma unroll
        for (int mi = 0; mi < 4; ++mi)
            #pragma unroll
            for (int h = 0; h < 2; ++h) {
                #pragma unroll
                for (int o = 1; o < 4; o <<= 1) {
                    st1[mi][h] += __shfl_xor_sync(0xFFFFFFFFu, st1[mi][h], o);
                    st2[mi][h] += __shfl_xor_sync(0xFFFFFFFFu, st2[mi][h], o);
                    st3[mi][h] += __shfl_xor_sync(0xFFFFFFFFu, st3[mi][h], o);
                }
            }
        if ((lane & 3) == 0) {
            #pragma unroll
            for (int mi = 0; mi < 4; ++mi)
                #pragma unroll
                for (int h = 0; h < 2; ++h) {
                    const int row = wm*64 + mi*16 + h*8 + r4;
                    float* p = sred + (wn*128 + row)*3;
                    p[0] = st1[mi][h]; p[1] = st2[mi][h]; p[2] = st3[mi][h];
                }
        }
        __syncthreads();
        {
            const int m = bm + tid;
            const int t8 = tile & 7;
            #pragma unroll
            for (int c = 0; c < 3; ++c)
                g_part[(c*8 + t8)*MROWS + m] =
                    sred[(0*128 + tid)*3 + c] + sred[(1*128 + tid)*3 + c];
        }
    }
}

// ===== Kernel 4 (merged): combine + mask pred + scatter + loss partial =====
__global__ void out_kernel(const float* __restrict__ expr,
                           const float* __restrict__ mask_token,
                           float* __restrict__ out_pred,
                           float* __restrict__ out_mask)
{
    const int b = blockIdx.x, tid = threadIdx.x;
    const int lane = tid & 31, wrp = tid >> 5;
    __shared__ float spred[KEEP];
    __shared__ float ws[24];
    __shared__ float s_cm;

    // --- mask_token pred via S1,S2,S3 + g_consts (same formula as combine) ---
    {
        float s1 = 0.f, s2 = 0.f, s3 = 0.f;
        #pragma unroll
        for (int i = 0; i < 4; ++i) {
            const int d = tid + i*256;
            const float x = mask_token[d];
            s1 += x; s2 += x*x; s3 += x*g_gw[d];
        }
        #pragma unroll
        for (int o = 16; o; o >>= 1) {
            s1 += __shfl_xor_sync(0xFFFFFFFFu, s1, o);
            s2 += __shfl_xor_sync(0xFFFFFFFFu, s2, o);
            s3 += __shfl_xor_sync(0xFFFFFFFFu, s3, o);
        }
        if (lane == 0) { ws[wrp] = s1; ws[8+wrp] = s2; ws[16+wrp] = s3; }
        __syncthreads();
        if (tid == 0) {
            float S1 = 0.f, S2 = 0.f, S3 = 0.f;
            #pragma unroll
            for (int i = 0; i < 8; ++i) { S1 += ws[i]; S2 += ws[8+i]; S3 += ws[16+i]; }
            const float mean = S1 * (1.0f/DIM);
            const float var  = S2 * (1.0f/DIM) - mean*mean;
            const float inv  = rsqrtf(var + LN_EPS);
            s_cm = inv*(S3 - mean*g_consts[0]) + g_consts[1];
        }
    }

    // --- combine this batch's 500 rows ---
    for (int m0 = tid; m0 < KEEP; m0 += 256) {
        const int m = b*KEEP + m0;
        float S1 = 0.f, S2 = 0.f, S3 = 0.f;
        #pragma unroll
        for (int t = 0; t < 8; ++t) {
            S1 += g_part[(0*8 + t)*MROWS + m];
            S2 += g_part[(1*8 + t)*MROWS + m];
            S3 += g_part[(2*8 + t)*MROWS + m];
        }
        const float mean = S1 * (1.0f/DIM);
        const float var  = S2 * (1.0f/DIM) - mean*mean;
        const float inv  = rsqrtf(var + LN_EPS);
        spred[m0] = inv*(S3 - mean*g_consts[0]) + g_consts[1];
    }
    __syncthreads();

    // --- scatter pred/mask + loss partial ---
    const float cm = s_cm;
    float part = 0.f;
    for (int l = tid; l < LSEQ; l += 256) {
        const int r = g_rank[b*LSEQ + l];
        const bool masked = (r >= KEEP);
        const float p = masked ? cm : spred[r];
        out_pred[b*LSEQ + l] = p;
        out_mask[b*LSEQ + l] = masked ? 1.0f : 0.0f;
        if (masked) {
            float t = expr[b*LSEQ + l];
            if (isnan(t)) t = 0.f;
            const float d = p - t;
            part += d*d;
        }
    }
    __shared__ float red[256];
    red[tid] = part; __syncthreads();
    #pragma unroll
    for (int o = 128; o > 0; o >>= 1) {
        if (tid < o) red[tid] += red[tid+o];
        __syncthreads();
    }
    if (tid == 0) g_losspart[b] = red[0];
}

// ===== Kernel 5: final loss =====
__global__ void loss_kernel(float* __restrict__ out)
{
    if (threadIdx.x == 0) {
        float s = 0.f;
        for (int i = 0; i < BATCH; ++i) s += g_losspart[i];
        out[0] = s / (float)NMASK;
    }
}

// =============================== launch ===============================
extern "C" void kernel_launch(void* const* d_in, const int* in_sizes, int n_in,
                              void* d_out, int out_size)
{
    const float* expr      = (const float*)d_in[0];
    const int*   idx       = (const int*)  d_in[1];
    const float* noise     = (const float*)d_in[2];
    const float* pos_table = (const float*)d_in[3];
    const float* cls_token = (const float*)d_in[4];
    const float* w_enc     = (const float*)d_in[5];
    const float* b_enc     = (const float*)d_in[6];
    const float* gamma1    = (const float*)d_in[7];
    const float* beta1     = (const float*)d_in[8];
    const float* W_dec     = (const float*)d_in[9];
    const float* b_dec     = (const float*)d_in[10];
    const float* mask_tok  = (const float*)d_in[11];
    const float* gamma2    = (const float*)d_in[12];
    const float* beta2     = (const float*)d_in[13];
    const float* W_pred    = (const float*)d_in[14];
    const float* b_pred    = (const float*)d_in[15];

    float* out = (float*)d_out;
    float* out_loss  = out;
    float* out_pred  = out + 1;
    float* out_mask  = out + 1 + BATCH*LSEQ;
    float* out_lat0  = out + 1 + 2*BATCH*LSEQ;

    cudaFuncSetAttribute(gemm_tc_kernel,
                         cudaFuncAttributeMaxDynamicSharedMemorySize, SMEM_TOTAL);

    setup_kernel<<<1281, 256>>>(noise, W_dec, gamma2, beta2, W_pred, b_pred);
    enc_ln_kernel<<<(BATCH*(KEEP+1))/8, 256>>>(expr, idx, pos_table, cls_token,
                                               w_enc, b_enc, gamma1, beta1, out_lat0);
    gemm_tc_kernel<<<GEMM_GRID, 128, SMEM_TOTAL>>>(b_dec);
    out_kernel<<<BATCH, 256>>>(expr, mask_tok, out_pred, out_mask);
    loss_kernel<<<1, 32>>>(out_loss);
}